// round 10
// baseline (speedup 1.0000x reference)
#include <cuda_runtime.h>
#include <cstdint>

typedef unsigned long long u64;
#define NTOT 65536
#define BATCH 2

__device__ __align__(16) float g_qkv1[(size_t)BATCH*384*NTOT];
__device__ __align__(16) float g_sa  [(size_t)BATCH*NTOT];
__device__ __align__(16) float g_v2  [(size_t)BATCH*128*NTOT];
__device__ float g_S[4096];
__device__ float g_ssq_q[256];
__device__ float g_ssq_k[256];
__device__ float g_sumv[256];
__device__ float g_attn[4096];
__device__ float g_spec[256];
__device__ __align__(16) u64 g_wq2[128*384];
__device__ __align__(16) u64 g_wp2[128*128];

__device__ __forceinline__ void fma2(u64 &d, u64 a, u64 b){
    asm("fma.rn.f32x2 %0, %1, %2, %0;" : "+l"(d) : "l"(a), "l"(b));
}
__device__ __forceinline__ float2 unpack2(u64 v){
    float2 r; asm("mov.b64 {%0, %1}, %2;" : "=f"(r.x), "=f"(r.y) : "l"(v)); return r;
}
__device__ __forceinline__ u64 pack2(float lo, float hi){
    u64 r; asm("mov.b64 %0, {%1, %2};" : "=l"(r) : "f"(lo), "f"(hi)); return r;
}
__device__ __forceinline__ void cp_async16(void* sdst, const void* gsrc){
    unsigned s = (unsigned)__cvta_generic_to_shared(sdst);
    asm volatile("cp.async.cg.shared.global [%0], [%1], 16;" :: "r"(s), "l"(gsrc));
}
__device__ __forceinline__ void cp_commit(){ asm volatile("cp.async.commit_group;"); }
__device__ __forceinline__ void cp_wait0(){ asm volatile("cp.async.wait_group 0;"); }
__device__ __forceinline__ float gelu_exact(float x){
    return 0.5f * x * (1.0f + erff(x * 0.70710678118654752f));
}

// ---- 4-wide single-row stencil over full 256-col row (t in [0,64)) — k2_dw ----
__device__ __forceinline__ void conv_acc4(float4& o, int valid, const float* row, int t,
                                          float w0, float w1, float w2){
    if (!valid) return;
    float4 a = __ldg((const float4*)(row + 4*t));
    float lf = __shfl_up_sync(0xffffffffu, a.w, 1);
    float rt = __shfl_down_sync(0xffffffffu, a.x, 1);
    int lane = t & 31;
    if (lane == 0)  lf = (t == 32) ? __ldg(row + 127) : 0.f;
    if (lane == 31) rt = (t == 31) ? __ldg(row + 128) : 0.f;
    o.x += w0*lf  + w1*a.x + w2*a.y;
    o.y += w0*a.x + w1*a.y + w2*a.z;
    o.z += w0*a.y + w1*a.z + w2*a.w;
    o.w += w0*a.z + w1*a.w + w2*rt;
}
__device__ __forceinline__ float4 conv3x4(const float* base, int r, int t, const float* w){
    float4 o = make_float4(0.f, 0.f, 0.f, 0.f);
    conv_acc4(o, r > 0,   base + (size_t)(r-1)*256, t, w[0], w[1], w[2]);
    conv_acc4(o, 1,       base + (size_t)r*256,     t, w[3], w[4], w[5]);
    conv_acc4(o, r < 255, base + (size_t)(r+1)*256, t, w[6], w[7], w[8]);
    return o;
}

// ---- warp-wide 128-col segment stencil (ln in [0,32), col0 in {0,128}) — k5_fused ----
struct R6 { float lf; float4 a; float rt; };
__device__ __forceinline__ R6 row_load(int valid, const float* row, int col0, int ln){
    R6 r;
    if (!valid){ r.lf = r.rt = 0.f; r.a = make_float4(0.f,0.f,0.f,0.f); return r; }
    const float* rp = row + col0;
    r.a = __ldg((const float4*)(rp + 4*ln));
    r.lf = __shfl_up_sync(0xffffffffu, r.a.w, 1);
    r.rt = __shfl_down_sync(0xffffffffu, r.a.x, 1);
    if (ln == 0)  r.lf = (col0 > 0)        ? __ldg(rp - 1)   : 0.f;
    if (ln == 31) r.rt = (col0 + 128 < 256)? __ldg(rp + 128) : 0.f;
    return r;
}
__device__ __forceinline__ void row_app(float4& o, const R6& r, float w0, float w1, float w2){
    o.x += w0*r.lf  + w1*r.a.x + w2*r.a.y;
    o.y += w0*r.a.x + w1*r.a.y + w2*r.a.z;
    o.z += w0*r.a.y + w1*r.a.z + w2*r.a.w;
    o.w += w0*r.a.z + w1*r.a.w + w2*r.rt;
}
__device__ __forceinline__ float4 conv3(const float* base, int r, int col0, int ln, const float* w){
    float4 o = make_float4(0.f,0.f,0.f,0.f);
    R6 t = row_load(r > 0,   base + (size_t)(r-1)*256, col0, ln); row_app(o, t, w[0], w[1], w[2]);
    t     = row_load(1,      base + (size_t)r*256,     col0, ln); row_app(o, t, w[3], w[4], w[5]);
    t     = row_load(r < 255,base + (size_t)(r+1)*256, col0, ln); row_app(o, t, w[6], w[7], w[8]);
    return o;
}

__global__ void k_prep(const float* __restrict__ qkv_w, const float* __restrict__ proj_w){
    int idx = blockIdx.x * 256 + threadIdx.x;
    if (idx < 49152){
        int o = idx % 384, i = idx / 384;
        unsigned b = __float_as_uint(qkv_w[o*128 + i]);
        g_wq2[idx] = ((u64)b << 32) | (u64)b;
    } else if (idx < 65536){
        int k = idx - 49152;
        int i = k >> 7, o = k & 127;
        unsigned b = __float_as_uint(proj_w[o*128 + i]);
        g_wp2[k] = ((u64)b << 32) | (u64)b;
    } else {
        int j = idx - 65536;
        if (j < 4096) g_S[j] = 0.f;
        else if (j < 4352) g_ssq_q[j-4096] = 0.f;
        else if (j < 4608) g_ssq_k[j-4352] = 0.f;
        else if (j < 4864) g_sumv [j-4608] = 0.f;
    }
}

__global__ void __launch_bounds__(256) k_sa(const float* __restrict__ y,
                                            const float* __restrict__ w1,
                                            const float* __restrict__ w2,
                                            const float* __restrict__ w3){
    __shared__ float sW1[128][16];
    __shared__ float sW2[16][16];
    __shared__ float sW3[16];
    int tid = threadIdx.x;
    int b = blockIdx.y;
    for (int i = tid; i < 2048; i += 256){ int c = i >> 4, j = i & 15; sW1[c][j] = w1[j*128 + c]; }
    (&sW2[0][0])[tid] = w2[tid];
    if (tid < 16) sW3[tid] = w3[tid];
    __syncthreads();

    int n0 = (blockIdx.x * 256 + tid) * 4;
    float acc[4][16];
#pragma unroll
    for (int p = 0; p < 4; p++)
#pragma unroll
        for (int j = 0; j < 16; j++) acc[p][j] = 0.f;

    const float* yb = y + (size_t)b * 128 * NTOT + n0;
    for (int c = 0; c < 128; c++){
        float4 yv = *(const float4*)(yb + (size_t)c * NTOT);
#pragma unroll
        for (int j = 0; j < 16; j++){
            float w = sW1[c][j];
            acc[0][j] += w * yv.x; acc[1][j] += w * yv.y;
            acc[2][j] += w * yv.z; acc[3][j] += w * yv.w;
        }
    }
    float out[4];
#pragma unroll
    for (int p = 0; p < 4; p++){
        float t2[16];
#pragma unroll
        for (int i = 0; i < 16; i++){
            float s = 0.f;
#pragma unroll
            for (int j = 0; j < 16; j++) s += sW2[i][j] * fmaxf(acc[p][j], 0.f);
            t2[i] = fmaxf(s, 0.f);
        }
        float s3 = 0.f;
#pragma unroll
        for (int j = 0; j < 16; j++) s3 += sW3[j] * t2[j];
        out[p] = 1.f / (1.f + expf(-s3));
    }
    *(float4*)(g_sa + (size_t)b * NTOT + n0) = make_float4(out[0], out[1], out[2], out[3]);
}

// qkv GEMM: C[M,N] = W[M,128] @ X[128,N] per batch; FFMA2 8x8 tile, cp.async double buffer
__global__ void __launch_bounds__(256, 2) k_gemm(const u64* __restrict__ w2,
                                                 const float* __restrict__ X,
                                                 float* __restrict__ C, int M){
    __shared__ u64 ws[2][16][128];
    __shared__ u64 xs[2][16][64];

    int tid = threadIdx.x;
    int b = blockIdx.z;
    int obase = blockIdx.y * 128;
    int nbase = blockIdx.x * 128;
    const float* x = X + (size_t)b * 128 * NTOT;
    float* c = C + (size_t)b * M * NTOT;
    int to8 = (tid >> 4) * 8;
    int tn4 = (tid & 15) * 4;

    auto load_chunk = [&](int kc, int buf){
#pragma unroll
        for (int t = 0; t < 4; t++){
            int e = t * 256 + tid;
            int k = e >> 6;
            int o = (2 * e) & 127;
            cp_async16(&ws[buf][k][o], w2 + (size_t)(kc*16 + k) * M + obase + o);
        }
#pragma unroll
        for (int t = 0; t < 2; t++){
            int e = t * 256 + tid;
            int k = e >> 5;
            int p = (2 * e) & 63;
            cp_async16(&xs[buf][k][p], x + (size_t)(kc*16 + k) * NTOT + nbase + 2*p);
        }
        cp_commit();
    };

    u64 acc[8][4];
#pragma unroll
    for (int o = 0; o < 8; o++)
#pragma unroll
        for (int p = 0; p < 4; p++) acc[o][p] = 0ULL;

    load_chunk(0, 0);
    cp_wait0(); __syncthreads();

    for (int kc = 0; kc < 8; kc++){
        int buf = kc & 1;
        if (kc < 7) load_chunk(kc + 1, buf ^ 1);
#pragma unroll
        for (int k = 0; k < 16; k++){
            u64 wv[8], xv[4];
#pragma unroll
            for (int j = 0; j < 4; j++){
                ulonglong2 t = *(const ulonglong2*)&ws[buf][k][to8 + 2*j];
                wv[2*j] = t.x; wv[2*j+1] = t.y;
            }
            {
                ulonglong2 t0 = *(const ulonglong2*)&xs[buf][k][tn4];
                ulonglong2 t1 = *(const ulonglong2*)&xs[buf][k][tn4 + 2];
                xv[0] = t0.x; xv[1] = t0.y; xv[2] = t1.x; xv[3] = t1.y;
            }
#pragma unroll
            for (int o = 0; o < 8; o++)
#pragma unroll
                for (int p = 0; p < 4; p++)
                    fma2(acc[o][p], wv[o], xv[p]);
        }
        if (kc < 7){ cp_wait0(); __syncthreads(); }
    }

#pragma unroll
    for (int o = 0; o < 8; o++){
        float2 f0 = unpack2(acc[o][0]), f1 = unpack2(acc[o][1]);
        float2 f2 = unpack2(acc[o][2]), f3 = unpack2(acc[o][3]);
        float* dst = c + (size_t)(obase + to8 + o) * NTOT + nbase + (tid & 15) * 8;
        *(float4*)(dst)     = make_float4(f0.x, f0.y, f1.x, f1.y);
        *(float4*)(dst + 4) = make_float4(f2.x, f2.y, f3.x, f3.y);
    }
}

// fused dwconv3x3 + sa gate + reductions + v write (R5 version: 1 row x 256 cols per block)
__global__ void __launch_bounds__(256) k2_dw(const float* __restrict__ qkv_dw_w){
    int tid = threadIdx.x;
    int r = blockIdx.x, h = blockIdx.y, b = blockIdx.z;
    int g = tid >> 6, t = tid & 63;
    __shared__ __align__(16) float qs[16][268];
    __shared__ __align__(16) float ks[16][268];
    __shared__ float sdw[48][9];
    __shared__ __align__(16) float s_sa[256];
    __shared__ float s_ssq_q[16], s_ssq_k[16], s_vsum[16];

    if (tid < 64)
        *(float4*)(s_sa + 4*tid) = *(const float4*)(g_sa + (size_t)b*NTOT + r*256 + 4*tid);
    for (int idx = tid; idx < 432; idx += 256){
        int lc = idx / 9, j = idx % 9;
        int ch = (lc < 16) ? (h*16 + lc) : (lc < 32 ? (128 + h*16 + (lc-16)) : (256 + h*16 + (lc-32)));
        sdw[lc][j] = qkv_dw_w[ch*9 + j];
    }
    if (tid < 16){ s_ssq_q[tid] = 0.f; s_ssq_k[tid] = 0.f; s_vsum[tid] = 0.f; }
    __syncthreads();

    float4 sa4 = *(const float4*)(s_sa + 4*t);
    int lane = tid & 31;

    for (int lc0 = 0; lc0 < 48; lc0 += 4){
        int lc = lc0 + g;
        int ch = (lc < 16) ? (h*16 + lc) : (lc < 32 ? (128 + h*16 + (lc-16)) : (256 + h*16 + (lc-32)));
        const float* base = g_qkv1 + ((size_t)b*384 + ch) * NTOT;
        float4 v = conv3x4(base, r, t, sdw[lc]);
        if (lc < 16){
            v.x *= sa4.x; v.y *= sa4.y; v.z *= sa4.z; v.w *= sa4.w;
            *(float4*)&qs[lc][4*t] = v;
            float sq = v.x*v.x + v.y*v.y + v.z*v.z + v.w*v.w;
#pragma unroll
            for (int o = 16; o; o >>= 1) sq += __shfl_down_sync(0xffffffffu, sq, o);
            if (lane == 0) atomicAdd(&s_ssq_q[lc], sq);
        } else if (lc < 32){
            *(float4*)&ks[lc-16][4*t] = v;
            float sq = v.x*v.x + v.y*v.y + v.z*v.z + v.w*v.w;
#pragma unroll
            for (int o = 16; o; o >>= 1) sq += __shfl_down_sync(0xffffffffu, sq, o);
            if (lane == 0) atomicAdd(&s_ssq_k[lc-16], sq);
        } else {
            *(float4*)(g_v2 + ((size_t)b*128 + h*16 + (lc-32)) * NTOT + r*256 + 4*t) = v;
            float sv = v.x + v.y + v.z + v.w;
#pragma unroll
            for (int o = 16; o; o >>= 1) sv += __shfl_down_sync(0xffffffffu, sv, o);
            if (lane == 0) atomicAdd(&s_vsum[lc-32], sv);
        }
    }
    __syncthreads();

    int c = tid >> 4, d = tid & 15;
    float s = 0.f;
#pragma unroll 8
    for (int i = 0; i < 64; i++){
        float4 qv = *(const float4*)&qs[c][4*i];
        float4 kv = *(const float4*)&ks[d][4*i];
        s += qv.x*kv.x + qv.y*kv.y + qv.z*kv.z + qv.w*kv.w;
    }
    atomicAdd(&g_S[((b*8 + h)*16 + c)*16 + d], s);

    if (tid < 16){
        atomicAdd(&g_ssq_q[b*128 + h*16 + tid], s_ssq_q[tid]);
        atomicAdd(&g_ssq_k[b*128 + h*16 + tid], s_ssq_k[tid]);
        atomicAdd(&g_sumv [b*128 + h*16 + tid], s_vsum[tid]);
    }
}

// softmax + spectral MLP (one block, 256 threads)
__global__ void k4_small(const float* __restrict__ sp_w1, const float* __restrict__ sp_w2,
                         const float* __restrict__ sp_w3, const float* __restrict__ temp){
    __shared__ float pooled[2][128];
    __shared__ float t1s[2][16], t2s[2][16];
    int t = threadIdx.x;
    int b = t >> 7, row = t & 127, h = row >> 4, c = row & 15;

    float nq = fmaxf(sqrtf(g_ssq_q[b*128 + row]), 1e-12f);
    float tmp = temp[h];
    float logits[16];
    float mx = -1e30f;
#pragma unroll
    for (int d = 0; d < 16; d++){
        float nk = fmaxf(sqrtf(g_ssq_k[b*128 + h*16 + d]), 1e-12f);
        float L = g_S[((b*8 + h)*16 + c)*16 + d] / (nq * nk) * tmp;
        logits[d] = L; mx = fmaxf(mx, L);
    }
    float se = 0.f;
#pragma unroll
    for (int d = 0; d < 16; d++){ float e = expf(logits[d] - mx); logits[d] = e; se += e; }
    float inv = 1.f / se;
    float pool = 0.f;
#pragma unroll
    for (int d = 0; d < 16; d++){
        float a = logits[d] * inv;
        g_attn[b*2048 + (h*16 + c)*16 + d] = a;
        pool += a * g_sumv[b*128 + h*16 + d];
    }
    pooled[b][row] = pool * (1.f / 65536.f);
    __syncthreads();
    if (t < 32){
        int bb = t >> 4, j = t & 15;
        float s = 0.f;
        for (int c2 = 0; c2 < 128; c2++) s += sp_w1[j*128 + c2] * pooled[bb][c2];
        t1s[bb][j] = gelu_exact(s);
    }
    __syncthreads();
    if (t < 32){
        int bb = t >> 4, j = t & 15;
        float s = 0.f;
#pragma unroll
        for (int i = 0; i < 16; i++) s += sp_w2[j*16 + i] * t1s[bb][i];
        t2s[bb][j] = gelu_exact(s);
    }
    __syncthreads();
    {
        int bb = t >> 7, ch = t & 127;
        float s = 0.f;
#pragma unroll
        for (int j = 0; j < 16; j++) s += sp_w3[ch*16 + j] * t2s[bb][j];
        g_spec[bb*128 + ch] = 1.f / (1.f + expf(-s));
    }
}

// fused: z = blockdiag(attn)@v + spec*dwconv(y)  -->  out = proj_w @ z   (z stays in smem)
// block = (r, nh, b): 1 row x 128 cols, all 128 channels; out tile [128 o][128 cols]
__global__ void __launch_bounds__(256) k5_fused(const float* __restrict__ y,
                                                const float* __restrict__ dw_w,
                                                float* __restrict__ out){
    int tid = threadIdx.x;
    int wp = tid >> 5, ln = tid & 31;
    int r = blockIdx.x, nh = blockIdx.y, b = blockIdx.z;
    int col0 = nh * 128;

    __shared__ float s_attn[2048];
    __shared__ float s_spec[128];
    __shared__ float s_dw[128][9];
    __shared__ __align__(16) float sv[16][128];
    __shared__ __align__(16) u64 zt[16][66];
    __shared__ __align__(16) u64 swp[16][128];

    for (int i = tid; i < 2048; i += 256) s_attn[i] = g_attn[b*2048 + i];
    for (int i = tid; i < 1152; i += 256) (&s_dw[0][0])[i] = dw_w[i];
    if (tid < 128) s_spec[tid] = g_spec[b*128 + tid];

    u64 acc[16][2];
#pragma unroll
    for (int i = 0; i < 16; i++){ acc[i][0] = 0ULL; acc[i][1] = 0ULL; }

    for (int h = 0; h < 8; h++){
        __syncthreads();   // previous head's zt/swp/sv fully consumed (and init loads done)
        for (int i = tid; i < 512; i += 256){
            int d = i >> 5, pp = i & 31;
            *(float4*)&sv[d][4*pp] =
                *(const float4*)(g_v2 + ((size_t)b*128 + h*16 + d) * NTOT + (size_t)r*256 + col0 + 4*pp);
        }
        for (int i = tid; i < 1024; i += 256){
            int cc = i >> 6, oo = (i & 63) * 2;
            *(ulonglong2*)&swp[cc][oo] = *(const ulonglong2*)&g_wp2[(h*16 + cc)*128 + oo];
        }
        __syncthreads();

#pragma unroll
        for (int half = 0; half < 2; half++){
            int cc = wp + 8*half;
            int ch = h*16 + cc;
            const float* ybase = y + ((size_t)b*128 + ch) * NTOT;
            float4 z = conv3(ybase, r, col0, ln, s_dw[ch]);
            float sp = s_spec[ch];
            z.x *= sp; z.y *= sp; z.z *= sp; z.w *= sp;
            const float* arow = &s_attn[ch * 16];
#pragma unroll
            for (int d = 0; d < 16; d++){
                float a = arow[d];
                float4 vd = *(const float4*)&sv[d][4*ln];
                z.x += a*vd.x; z.y += a*vd.y; z.z += a*vd.z; z.w += a*vd.w;
            }
            zt[cc][2*ln]     = pack2(z.x, z.y);
            zt[cc][2*ln + 1] = pack2(z.z, z.w);
        }
        __syncthreads();

#pragma unroll 1
        for (int cc = 0; cc < 16; cc++){
            ulonglong2 zz = *(const ulonglong2*)&zt[cc][2*ln];
            const u64* wrow = &swp[cc][wp*16];
#pragma unroll
            for (int i = 0; i < 8; i++){
                ulonglong2 wv = *(const ulonglong2*)&wrow[2*i];
                fma2(acc[2*i  ][0], wv.x, zz.x);
                fma2(acc[2*i  ][1], wv.x, zz.y);
                fma2(acc[2*i+1][0], wv.y, zz.x);
                fma2(acc[2*i+1][1], wv.y, zz.y);
            }
        }
    }

#pragma unroll
    for (int i = 0; i < 16; i++){
        float2 f0 = unpack2(acc[i][0]);
        float2 f1 = unpack2(acc[i][1]);
        *(float4*)(out + ((size_t)b*128 + wp*16 + i) * NTOT + (size_t)r*256 + col0 + 4*ln)
            = make_float4(f0.x, f0.y, f1.x, f1.y);
    }
}

extern "C" void kernel_launch(void* const* d_in, const int* in_sizes, int n_in,
                              void* d_out, int out_size){
    const float* x        = (const float*)d_in[0];
    const float* y        = (const float*)d_in[1];
    const float* qkv_w    = (const float*)d_in[2];
    const float* qkv_dw_w = (const float*)d_in[3];
    const float* proj_w   = (const float*)d_in[4];
    const float* sa_w1    = (const float*)d_in[5];
    const float* sa_w2    = (const float*)d_in[6];
    const float* sa_w3    = (const float*)d_in[7];
    const float* sp_w1    = (const float*)d_in[8];
    const float* sp_w2    = (const float*)d_in[9];
    const float* sp_w3    = (const float*)d_in[10];
    const float* dw_w     = (const float*)d_in[11];
    const float* temp     = (const float*)d_in[12];
    float* out = (float*)d_out;

    u64 *wq2;
    float *qkv1;
    cudaGetSymbolAddress((void**)&wq2,  g_wq2);
    cudaGetSymbolAddress((void**)&qkv1, g_qkv1);

    k_prep<<<276, 256>>>(qkv_w, proj_w);
    k_sa<<<dim3(64, 2), 256>>>(y, sa_w1, sa_w2, sa_w3);
    k_gemm<<<dim3(512, 3, 2), 256>>>(wq2, x, qkv1, 384);
    k2_dw<<<dim3(256, 8, 2), 256>>>(qkv_dw_w);
    k4_small<<<1, 256>>>(sp_w1, sp_w2, sp_w3, temp);
    k5_fused<<<dim3(256, 2, 2), 256>>>(y, dw_w, out);
}

// round 12
// speedup vs baseline: 1.0949x; 1.0949x over previous
#include <cuda_runtime.h>
#include <cstdint>

typedef unsigned long long u64;
#define NTOT 65536
#define BATCH 2

__device__ __align__(16) float g_qkv1[(size_t)BATCH*384*NTOT];
__device__ __align__(16) float g_sa  [(size_t)BATCH*NTOT];
__device__ __align__(16) float g_v2  [(size_t)BATCH*128*NTOT];
__device__ __align__(16) float g_z   [(size_t)BATCH*128*NTOT];
__device__ float g_S[4096];
__device__ float g_ssq_q[256];
__device__ float g_ssq_k[256];
__device__ float g_sumv[256];
__device__ float g_attn[4096];
__device__ float g_spec[256];
__device__ __align__(16) u64 g_wq2[128*384];
__device__ __align__(16) u64 g_wp2[128*128];

__device__ __forceinline__ void fma2(u64 &d, u64 a, u64 b){
    asm("fma.rn.f32x2 %0, %1, %2, %0;" : "+l"(d) : "l"(a), "l"(b));
}
__device__ __forceinline__ float2 unpack2(u64 v){
    float2 r; asm("mov.b64 {%0, %1}, %2;" : "=f"(r.x), "=f"(r.y) : "l"(v)); return r;
}
__device__ __forceinline__ void cp_async16(void* sdst, const void* gsrc){
    unsigned s = (unsigned)__cvta_generic_to_shared(sdst);
    asm volatile("cp.async.cg.shared.global [%0], [%1], 16;" :: "r"(s), "l"(gsrc));
}
__device__ __forceinline__ void cp_commit(){ asm volatile("cp.async.commit_group;"); }
__device__ __forceinline__ void cp_wait0(){ asm volatile("cp.async.wait_group 0;"); }
__device__ __forceinline__ float gelu_exact(float x){
    return 0.5f * x * (1.0f + erff(x * 0.70710678118654752f));
}

// ---- 4-wide single-row stencil over full 256-col row (t in [0,64)) ----
__device__ __forceinline__ void conv_acc4(float4& o, int valid, const float* row, int t,
                                          float w0, float w1, float w2){
    if (!valid) return;
    float4 a = __ldg((const float4*)(row + 4*t));
    float lf = __shfl_up_sync(0xffffffffu, a.w, 1);
    float rt = __shfl_down_sync(0xffffffffu, a.x, 1);
    int lane = t & 31;
    if (lane == 0)  lf = (t == 32) ? __ldg(row + 127) : 0.f;
    if (lane == 31) rt = (t == 31) ? __ldg(row + 128) : 0.f;
    o.x += w0*lf  + w1*a.x + w2*a.y;
    o.y += w0*a.x + w1*a.y + w2*a.z;
    o.z += w0*a.y + w1*a.z + w2*a.w;
    o.w += w0*a.z + w1*a.w + w2*rt;
}
__device__ __forceinline__ float4 conv3x4(const float* base, int r, int t, const float* w){
    float4 o = make_float4(0.f, 0.f, 0.f, 0.f);
    conv_acc4(o, r > 0,   base + (size_t)(r-1)*256, t, w[0], w[1], w[2]);
    conv_acc4(o, 1,       base + (size_t)r*256,     t, w[3], w[4], w[5]);
    conv_acc4(o, r < 255, base + (size_t)(r+1)*256, t, w[6], w[7], w[8]);
    return o;
}

__global__ void k_prep(const float* __restrict__ qkv_w, const float* __restrict__ proj_w){
    int idx = blockIdx.x * 256 + threadIdx.x;
    if (idx < 49152){
        int o = idx % 384, i = idx / 384;
        unsigned b = __float_as_uint(qkv_w[o*128 + i]);
        g_wq2[idx] = ((u64)b << 32) | (u64)b;
    } else if (idx < 65536){
        int k = idx - 49152;
        int i = k >> 7, o = k & 127;
        unsigned b = __float_as_uint(proj_w[o*128 + i]);
        g_wp2[k] = ((u64)b << 32) | (u64)b;
    } else {
        int j = idx - 65536;
        if (j < 4096) g_S[j] = 0.f;
        else if (j < 4352) g_ssq_q[j-4096] = 0.f;
        else if (j < 4608) g_ssq_k[j-4352] = 0.f;
        else if (j < 4864) g_sumv [j-4608] = 0.f;
    }
}

// spatial gate: 2 px per thread, 256 blocks total -> ~14 warps/SM
__global__ void __launch_bounds__(256) k_sa(const float* __restrict__ y,
                                            const float* __restrict__ w1,
                                            const float* __restrict__ w2,
                                            const float* __restrict__ w3){
    __shared__ float sW1[128][16];
    __shared__ float sW2[16][16];
    __shared__ float sW3[16];
    int tid = threadIdx.x;
    int b = blockIdx.y;
    for (int i = tid; i < 2048; i += 256){ int c = i >> 4, j = i & 15; sW1[c][j] = w1[j*128 + c]; }
    (&sW2[0][0])[tid] = w2[tid];
    if (tid < 16) sW3[tid] = w3[tid];
    __syncthreads();

    int n0 = (blockIdx.x * 256 + tid) * 2;
    float acc[2][16];
#pragma unroll
    for (int p = 0; p < 2; p++)
#pragma unroll
        for (int j = 0; j < 16; j++) acc[p][j] = 0.f;

    const float* yb = y + (size_t)b * 128 * NTOT + n0;
#pragma unroll 4
    for (int c = 0; c < 128; c++){
        float2 yv = *(const float2*)(yb + (size_t)c * NTOT);
#pragma unroll
        for (int j = 0; j < 16; j++){
            float w = sW1[c][j];
            acc[0][j] += w * yv.x; acc[1][j] += w * yv.y;
        }
    }
    float out[2];
#pragma unroll
    for (int p = 0; p < 2; p++){
        float t2[16];
#pragma unroll
        for (int i = 0; i < 16; i++){
            float s = 0.f;
#pragma unroll
            for (int j = 0; j < 16; j++) s += sW2[i][j] * fmaxf(acc[p][j], 0.f);
            t2[i] = fmaxf(s, 0.f);
        }
        float s3 = 0.f;
#pragma unroll
        for (int j = 0; j < 16; j++) s3 += sW3[j] * t2[j];
        out[p] = 1.f / (1.f + expf(-s3));
    }
    *(float2*)(g_sa + (size_t)b * NTOT + n0) = make_float2(out[0], out[1]);
}

// C[M,N] = W[M,128] @ X[128,N] per batch; FFMA2 8x8 tile, cp.async double buffer
__global__ void __launch_bounds__(256, 2) k_gemm(const u64* __restrict__ w2,
                                                 const float* __restrict__ X,
                                                 float* __restrict__ C, int M){
    __shared__ u64 ws[2][16][128];
    __shared__ u64 xs[2][16][64];

    int tid = threadIdx.x;
    int b = blockIdx.z;
    int obase = blockIdx.y * 128;
    int nbase = blockIdx.x * 128;
    const float* x = X + (size_t)b * 128 * NTOT;
    float* c = C + (size_t)b * M * NTOT;
    int to8 = (tid >> 4) * 8;
    int tn4 = (tid & 15) * 4;

    auto load_chunk = [&](int kc, int buf){
#pragma unroll
        for (int t = 0; t < 4; t++){
            int e = t * 256 + tid;
            int k = e >> 6;
            int o = (2 * e) & 127;
            cp_async16(&ws[buf][k][o], w2 + (size_t)(kc*16 + k) * M + obase + o);
        }
#pragma unroll
        for (int t = 0; t < 2; t++){
            int e = t * 256 + tid;
            int k = e >> 5;
            int p = (2 * e) & 63;
            cp_async16(&xs[buf][k][p], x + (size_t)(kc*16 + k) * NTOT + nbase + 2*p);
        }
        cp_commit();
    };

    u64 acc[8][4];
#pragma unroll
    for (int o = 0; o < 8; o++)
#pragma unroll
        for (int p = 0; p < 4; p++) acc[o][p] = 0ULL;

    load_chunk(0, 0);
    cp_wait0(); __syncthreads();

    for (int kc = 0; kc < 8; kc++){
        int buf = kc & 1;
        if (kc < 7) load_chunk(kc + 1, buf ^ 1);
#pragma unroll
        for (int k = 0; k < 16; k++){
            u64 wv[8], xv[4];
#pragma unroll
            for (int j = 0; j < 4; j++){
                ulonglong2 t = *(const ulonglong2*)&ws[buf][k][to8 + 2*j];
                wv[2*j] = t.x; wv[2*j+1] = t.y;
            }
            {
                ulonglong2 t0 = *(const ulonglong2*)&xs[buf][k][tn4];
                ulonglong2 t1 = *(const ulonglong2*)&xs[buf][k][tn4 + 2];
                xv[0] = t0.x; xv[1] = t0.y; xv[2] = t1.x; xv[3] = t1.y;
            }
#pragma unroll
            for (int o = 0; o < 8; o++)
#pragma unroll
                for (int p = 0; p < 4; p++)
                    fma2(acc[o][p], wv[o], xv[p]);
        }
        if (kc < 7){ cp_wait0(); __syncthreads(); }
    }

#pragma unroll
    for (int o = 0; o < 8; o++){
        float2 f0 = unpack2(acc[o][0]), f1 = unpack2(acc[o][1]);
        float2 f2 = unpack2(acc[o][2]), f3 = unpack2(acc[o][3]);
        float* dst = c + (size_t)(obase + to8 + o) * NTOT + nbase + (tid & 15) * 8;
        *(float4*)(dst)     = make_float4(f0.x, f0.y, f1.x, f1.y);
        *(float4*)(dst + 4) = make_float4(f2.x, f2.y, f3.x, f3.y);
    }
}

// fused dwconv3x3 + sa gate + reductions + v write (R5 version)
__global__ void __launch_bounds__(256) k2_dw(const float* __restrict__ qkv_dw_w){
    int tid = threadIdx.x;
    int r = blockIdx.x, h = blockIdx.y, b = blockIdx.z;
    int g = tid >> 6, t = tid & 63;
    __shared__ __align__(16) float qs[16][268];
    __shared__ __align__(16) float ks[16][268];
    __shared__ float sdw[48][9];
    __shared__ __align__(16) float s_sa[256];
    __shared__ float s_ssq_q[16], s_ssq_k[16], s_vsum[16];

    if (tid < 64)
        *(float4*)(s_sa + 4*tid) = *(const float4*)(g_sa + (size_t)b*NTOT + r*256 + 4*tid);
    for (int idx = tid; idx < 432; idx += 256){
        int lc = idx / 9, j = idx % 9;
        int ch = (lc < 16) ? (h*16 + lc) : (lc < 32 ? (128 + h*16 + (lc-16)) : (256 + h*16 + (lc-32)));
        sdw[lc][j] = qkv_dw_w[ch*9 + j];
    }
    if (tid < 16){ s_ssq_q[tid] = 0.f; s_ssq_k[tid] = 0.f; s_vsum[tid] = 0.f; }
    __syncthreads();

    float4 sa4 = *(const float4*)(s_sa + 4*t);
    int lane = tid & 31;

    for (int lc0 = 0; lc0 < 48; lc0 += 4){
        int lc = lc0 + g;
        int ch = (lc < 16) ? (h*16 + lc) : (lc < 32 ? (128 + h*16 + (lc-16)) : (256 + h*16 + (lc-32)));
        const float* base = g_qkv1 + ((size_t)b*384 + ch) * NTOT;
        float4 v = conv3x4(base, r, t, sdw[lc]);
        if (lc < 16){
            v.x *= sa4.x; v.y *= sa4.y; v.z *= sa4.z; v.w *= sa4.w;
            *(float4*)&qs[lc][4*t] = v;
            float sq = v.x*v.x + v.y*v.y + v.z*v.z + v.w*v.w;
#pragma unroll
            for (int o = 16; o; o >>= 1) sq += __shfl_down_sync(0xffffffffu, sq, o);
            if (lane == 0) atomicAdd(&s_ssq_q[lc], sq);
        } else if (lc < 32){
            *(float4*)&ks[lc-16][4*t] = v;
            float sq = v.x*v.x + v.y*v.y + v.z*v.z + v.w*v.w;
#pragma unroll
            for (int o = 16; o; o >>= 1) sq += __shfl_down_sync(0xffffffffu, sq, o);
            if (lane == 0) atomicAdd(&s_ssq_k[lc-16], sq);
        } else {
            *(float4*)(g_v2 + ((size_t)b*128 + h*16 + (lc-32)) * NTOT + r*256 + 4*t) = v;
            float sv = v.x + v.y + v.z + v.w;
#pragma unroll
            for (int o = 16; o; o >>= 1) sv += __shfl_down_sync(0xffffffffu, sv, o);
            if (lane == 0) atomicAdd(&s_vsum[lc-32], sv);
        }
    }
    __syncthreads();

    int c = tid >> 4, d = tid & 15;
    float s = 0.f;
#pragma unroll 8
    for (int i = 0; i < 64; i++){
        float4 qv = *(const float4*)&qs[c][4*i];
        float4 kv = *(const float4*)&ks[d][4*i];
        s += qv.x*kv.x + qv.y*kv.y + qv.z*kv.z + qv.w*kv.w;
    }
    atomicAdd(&g_S[((b*8 + h)*16 + c)*16 + d], s);

    if (tid < 16){
        atomicAdd(&g_ssq_q[b*128 + h*16 + tid], s_ssq_q[tid]);
        atomicAdd(&g_ssq_k[b*128 + h*16 + tid], s_ssq_k[tid]);
        atomicAdd(&g_sumv [b*128 + h*16 + tid], s_vsum[tid]);
    }
}

// softmax + spectral MLP (one block, 256 threads)
__global__ void k4_small(const float* __restrict__ sp_w1, const float* __restrict__ sp_w2,
                         const float* __restrict__ sp_w3, const float* __restrict__ temp){
    __shared__ float pooled[2][128];
    __shared__ float t1s[2][16], t2s[2][16];
    int t = threadIdx.x;
    int b = t >> 7, row = t & 127, h = row >> 4, c = row & 15;

    float nq = fmaxf(sqrtf(g_ssq_q[b*128 + row]), 1e-12f);
    float tmp = temp[h];
    float logits[16];
    float mx = -1e30f;
#pragma unroll
    for (int d = 0; d < 16; d++){
        float nk = fmaxf(sqrtf(g_ssq_k[b*128 + h*16 + d]), 1e-12f);
        float L = g_S[((b*8 + h)*16 + c)*16 + d] / (nq * nk) * tmp;
        logits[d] = L; mx = fmaxf(mx, L);
    }
    float se = 0.f;
#pragma unroll
    for (int d = 0; d < 16; d++){ float e = expf(logits[d] - mx); logits[d] = e; se += e; }
    float inv = 1.f / se;
    float pool = 0.f;
#pragma unroll
    for (int d = 0; d < 16; d++){
        float a = logits[d] * inv;
        g_attn[b*2048 + (h*16 + c)*16 + d] = a;
        pool += a * g_sumv[b*128 + h*16 + d];
    }
    pooled[b][row] = pool * (1.f / 65536.f);
    __syncthreads();
    if (t < 32){
        int bb = t >> 4, j = t & 15;
        float s = 0.f;
        for (int c2 = 0; c2 < 128; c2++) s += sp_w1[j*128 + c2] * pooled[bb][c2];
        t1s[bb][j] = gelu_exact(s);
    }
    __syncthreads();
    if (t < 32){
        int bb = t >> 4, j = t & 15;
        float s = 0.f;
#pragma unroll
        for (int i = 0; i < 16; i++) s += sp_w2[j*16 + i] * t1s[bb][i];
        t2s[bb][j] = gelu_exact(s);
    }
    __syncthreads();
    {
        int bb = t >> 7, ch = t & 127;
        float s = 0.f;
#pragma unroll
        for (int j = 0; j < 16; j++) s += sp_w3[ch*16 + j] * t2s[bb][j];
        g_spec[bb*128 + ch] = 1.f / (1.f + expf(-s));
    }
}

// z = blockdiag(attn) @ v + spec * dwconv3x3(y); v tile staged in smem per head
__global__ void __launch_bounds__(256) k5a_z(const float* __restrict__ y,
                                             const float* __restrict__ dw_w){
    int tid = threadIdx.x;
    int r = blockIdx.x, b = blockIdx.y;
    int g = tid >> 6, t = tid & 63;
    __shared__ float s_attn[2048];
    __shared__ float s_spec[128];
    __shared__ float s_dw[128][9];
    __shared__ __align__(16) float sv[16][256];
    for (int i = tid; i < 2048; i += 256) s_attn[i] = g_attn[b*2048 + i];
    for (int i = tid; i < 1152; i += 256) (&s_dw[0][0])[i] = dw_w[i];
    if (tid < 128) s_spec[tid] = g_spec[b*128 + tid];
    __syncthreads();

    for (int h = 0; h < 8; h++){
        for (int i = tid; i < 1024; i += 256){
            int d = i >> 6, p = i & 63;
            *(float4*)&sv[d][4*p] =
                *(const float4*)(g_v2 + ((size_t)b*128 + h*16 + d) * NTOT + r*256 + 4*p);
        }
        __syncthreads();
#pragma unroll
        for (int cc = 0; cc < 4; cc++){
            int c = cc*4 + g;
            int ch = h*16 + c;
            const float* ybase = y + ((size_t)b*128 + ch) * NTOT;
            float4 z = conv3x4(ybase, r, t, s_dw[ch]);
            float sp = s_spec[ch];
            z.x *= sp; z.y *= sp; z.z *= sp; z.w *= sp;
            const float* arow = &s_attn[ch * 16];
#pragma unroll
            for (int d = 0; d < 16; d++){
                float a = arow[d];
                float4 vd = *(const float4*)&sv[d][4*t];
                z.x += a*vd.x; z.y += a*vd.y; z.z += a*vd.z; z.w += a*vd.w;
            }
            *(float4*)(g_z + ((size_t)b*128 + ch) * NTOT + r*256 + 4*t) = z;
        }
        __syncthreads();
    }
}

extern "C" void kernel_launch(void* const* d_in, const int* in_sizes, int n_in,
                              void* d_out, int out_size){
    const float* x        = (const float*)d_in[0];
    const float* y        = (const float*)d_in[1];
    const float* qkv_w    = (const float*)d_in[2];
    const float* qkv_dw_w = (const float*)d_in[3];
    const float* proj_w   = (const float*)d_in[4];
    const float* sa_w1    = (const float*)d_in[5];
    const float* sa_w2    = (const float*)d_in[6];
    const float* sa_w3    = (const float*)d_in[7];
    const float* sp_w1    = (const float*)d_in[8];
    const float* sp_w2    = (const float*)d_in[9];
    const float* sp_w3    = (const float*)d_in[10];
    const float* dw_w     = (const float*)d_in[11];
    const float* temp     = (const float*)d_in[12];
    float* out = (float*)d_out;

    u64 *wq2, *wp2;
    float *qkv1, *z;
    cudaGetSymbolAddress((void**)&wq2,  g_wq2);
    cudaGetSymbolAddress((void**)&wp2,  g_wp2);
    cudaGetSymbolAddress((void**)&qkv1, g_qkv1);
    cudaGetSymbolAddress((void**)&z,    g_z);

    k_prep<<<276, 256>>>(qkv_w, proj_w);
    k_sa<<<dim3(128, 2), 256>>>(y, sa_w1, sa_w2, sa_w3);
    k_gemm<<<dim3(512, 3, 2), 256>>>(wq2, x, qkv1, 384);
    k2_dw<<<dim3(256, 8, 2), 256>>>(qkv_dw_w);
    k4_small<<<1, 256>>>(sp_w1, sp_w2, sp_w3, temp);
    k5a_z<<<dim3(256, 2), 256>>>(y, dw_w);
    k_gemm<<<dim3(512, 1, 2), 256>>>(wp2, z, out, 128);
}

// round 13
// speedup vs baseline: 1.4150x; 1.2923x over previous
#include <cuda_runtime.h>
#include <cuda_bf16.h>
#include <cstdint>

typedef unsigned long long u64;
#define NTOT 65536
#define BATCH 2

__device__ __align__(16) float g_qkv1[(size_t)BATCH*384*NTOT];
__device__ __align__(16) float g_sa  [(size_t)BATCH*NTOT];
__device__ __align__(16) float g_v2  [(size_t)BATCH*128*NTOT];
__device__ __align__(16) float g_z   [(size_t)BATCH*128*NTOT];
__device__ float g_S[4096];
__device__ float g_ssq_q[256];
__device__ float g_ssq_k[256];
__device__ float g_sumv[256];
__device__ float g_attn[4096];
__device__ float g_spec[256];
__device__ __align__(16) u64 g_wp2[128*128];
// precomputed qkv_w mma A-fragments: [hi/lo][mtile][m16-tile][kstep][lane] = {a0,a1,a2,a3}
__device__ __align__(16) uint4 g_wfrag[2][3][8][8][32];

__device__ __forceinline__ void fma2(u64 &d, u64 a, u64 b){
    asm("fma.rn.f32x2 %0, %1, %2, %0;" : "+l"(d) : "l"(a), "l"(b));
}
__device__ __forceinline__ float2 unpack2(u64 v){
    float2 r; asm("mov.b64 {%0, %1}, %2;" : "=f"(r.x), "=f"(r.y) : "l"(v)); return r;
}
__device__ __forceinline__ void cp_async16(void* sdst, const void* gsrc){
    unsigned s = (unsigned)__cvta_generic_to_shared(sdst);
    asm volatile("cp.async.cg.shared.global [%0], [%1], 16;" :: "r"(s), "l"(gsrc));
}
__device__ __forceinline__ void cp_commit(){ asm volatile("cp.async.commit_group;"); }
__device__ __forceinline__ void cp_wait0(){ asm volatile("cp.async.wait_group 0;"); }
__device__ __forceinline__ float gelu_exact(float x){
    return 0.5f * x * (1.0f + erff(x * 0.70710678118654752f));
}
__device__ __forceinline__ uint32_t smem_u32(const void* p){
    uint32_t a;
    asm("{ .reg .u64 t; cvta.to.shared.u64 t, %1; cvt.u32.u64 %0, t; }" : "=r"(a) : "l"(p));
    return a;
}
__device__ __forceinline__ void mma_bf16(float (&c)[4], const uint4& a, const uint32_t* b){
    asm volatile("mma.sync.aligned.m16n8k16.row.col.f32.bf16.bf16.f32 "
        "{%0,%1,%2,%3}, {%4,%5,%6,%7}, {%8,%9}, {%0,%1,%2,%3};"
        : "+f"(c[0]), "+f"(c[1]), "+f"(c[2]), "+f"(c[3])
        : "r"(a.x), "r"(a.y), "r"(a.z), "r"(a.w), "r"(b[0]), "r"(b[1]));
}
__device__ __forceinline__ void ldm_x2_t(uint32_t& r0, uint32_t& r1, uint32_t addr){
    asm volatile("ldmatrix.sync.aligned.m8n8.x2.trans.shared.b16 {%0,%1}, [%2];"
        : "=r"(r0), "=r"(r1) : "r"(addr));
}
__device__ __forceinline__ unsigned short bfc(float v, int lo){
    __nv_bfloat16 h = __float2bfloat16(v);
    if (lo){ float res = v - __bfloat162float(h); h = __float2bfloat16(res); }
    return __bfloat16_as_ushort(h);
}

// ---- 4-wide single-row stencil over full 256-col row (t in [0,64)) ----
__device__ __forceinline__ void conv_acc4(float4& o, int valid, const float* row, int t,
                                          float w0, float w1, float w2){
    if (!valid) return;
    float4 a = __ldg((const float4*)(row + 4*t));
    float lf = __shfl_up_sync(0xffffffffu, a.w, 1);
    float rt = __shfl_down_sync(0xffffffffu, a.x, 1);
    int lane = t & 31;
    if (lane == 0)  lf = (t == 32) ? __ldg(row + 127) : 0.f;
    if (lane == 31) rt = (t == 31) ? __ldg(row + 128) : 0.f;
    o.x += w0*lf  + w1*a.x + w2*a.y;
    o.y += w0*a.x + w1*a.y + w2*a.z;
    o.z += w0*a.y + w1*a.z + w2*a.w;
    o.w += w0*a.z + w1*a.w + w2*rt;
}
__device__ __forceinline__ float4 conv3x4(const float* base, int r, int t, const float* w){
    float4 o = make_float4(0.f, 0.f, 0.f, 0.f);
    conv_acc4(o, r > 0,   base + (size_t)(r-1)*256, t, w[0], w[1], w[2]);
    conv_acc4(o, 1,       base + (size_t)r*256,     t, w[3], w[4], w[5]);
    conv_acc4(o, r < 255, base + (size_t)(r+1)*256, t, w[6], w[7], w[8]);
    return o;
}

__global__ void k_prep(const float* __restrict__ qkv_w, const float* __restrict__ proj_w){
    int idx = blockIdx.x * 256 + threadIdx.x;
    if (idx < 16384){
        int i = idx >> 7, o = idx & 127;
        unsigned b = __float_as_uint(proj_w[o*128 + i]);
        g_wp2[idx] = ((u64)b << 32) | (u64)b;
    } else if (idx < 21248){
        int j = idx - 16384;
        if (j < 4096) g_S[j] = 0.f;
        else if (j < 4352) g_ssq_q[j-4096] = 0.f;
        else if (j < 4608) g_ssq_k[j-4352] = 0.f;
        else if (j < 4864) g_sumv [j-4608] = 0.f;
    } else {
        int t = idx - 21248;          // 0..12287
        int lane = t & 31; t >>= 5;
        int ks = t & 7;   t >>= 3;
        int mm = t & 7;   t >>= 3;
        int mt = t % 3;
        int hl = t / 3;
        int gid = lane >> 2, tig = lane & 3;
        int row0 = mt*128 + mm*16 + gid;
        int k0 = ks*16 + 2*tig;
        uint32_t a0 = (uint32_t)bfc(qkv_w[row0*128 + k0], hl)
                    | ((uint32_t)bfc(qkv_w[row0*128 + k0 + 1], hl) << 16);
        uint32_t a1 = (uint32_t)bfc(qkv_w[(row0+8)*128 + k0], hl)
                    | ((uint32_t)bfc(qkv_w[(row0+8)*128 + k0 + 1], hl) << 16);
        uint32_t a2 = (uint32_t)bfc(qkv_w[row0*128 + k0 + 8], hl)
                    | ((uint32_t)bfc(qkv_w[row0*128 + k0 + 9], hl) << 16);
        uint32_t a3 = (uint32_t)bfc(qkv_w[(row0+8)*128 + k0 + 8], hl)
                    | ((uint32_t)bfc(qkv_w[(row0+8)*128 + k0 + 9], hl) << 16);
        g_wfrag[hl][mt][mm][ks][lane] = make_uint4(a0, a1, a2, a3);
    }
}

// spatial gate: 2 px per thread, 256 blocks total
__global__ void __launch_bounds__(256) k_sa(const float* __restrict__ y,
                                            const float* __restrict__ w1,
                                            const float* __restrict__ w2,
                                            const float* __restrict__ w3){
    __shared__ float sW1[128][16];
    __shared__ float sW2[16][16];
    __shared__ float sW3[16];
    int tid = threadIdx.x;
    int b = blockIdx.y;
    for (int i = tid; i < 2048; i += 256){ int c = i >> 4, j = i & 15; sW1[c][j] = w1[j*128 + c]; }
    (&sW2[0][0])[tid] = w2[tid];
    if (tid < 16) sW3[tid] = w3[tid];
    __syncthreads();

    int n0 = (blockIdx.x * 256 + tid) * 2;
    float acc[2][16];
#pragma unroll
    for (int p = 0; p < 2; p++)
#pragma unroll
        for (int j = 0; j < 16; j++) acc[p][j] = 0.f;

    const float* yb = y + (size_t)b * 128 * NTOT + n0;
#pragma unroll 4
    for (int c = 0; c < 128; c++){
        float2 yv = *(const float2*)(yb + (size_t)c * NTOT);
#pragma unroll
        for (int j = 0; j < 16; j++){
            float w = sW1[c][j];
            acc[0][j] += w * yv.x; acc[1][j] += w * yv.y;
        }
    }
    float out[2];
#pragma unroll
    for (int p = 0; p < 2; p++){
        float t2[16];
#pragma unroll
        for (int i = 0; i < 16; i++){
            float s = 0.f;
#pragma unroll
            for (int j = 0; j < 16; j++) s += sW2[i][j] * fmaxf(acc[p][j], 0.f);
            t2[i] = fmaxf(s, 0.f);
        }
        float s3 = 0.f;
#pragma unroll
        for (int j = 0; j < 16; j++) s3 += sW3[j] * t2[j];
        out[p] = 1.f / (1.f + expf(-s3));
    }
    *(float2*)(g_sa + (size_t)b * NTOT + n0) = make_float2(out[0], out[1]);
}

// ===== qkv GEMM on tensor cores: C[384,N] = W @ X, bf16-split mma.sync =====
// block: 128M x 64N tile; 8 warps = 4M x 2N; warp tile 32M x 32N.
__global__ void __launch_bounds__(256) k_qkv_mma(const float* __restrict__ X,
                                                 float* __restrict__ C){
    __shared__ __align__(16) unsigned char sB[2][16384];  // bf16 hi/lo X tile [128k][64n], swizzled
    int tid = threadIdx.x;
    int nb = blockIdx.x, mt = blockIdx.y, b = blockIdx.z;
    int n0blk = nb * 64;
    const float* x = X + (size_t)b * 128 * NTOT;

    // convert X tile f32 -> bf16 hi/lo into swizzled smem
#pragma unroll
    for (int j = 0; j < 8; j++){
        int i = j*256 + tid;
        int k = i >> 4;             // 0..127
        int n0 = (i & 15) * 4;      // 0..60
        float4 v = *(const float4*)(x + (size_t)k*NTOT + n0blk + n0);
        unsigned short h0 = bfc(v.x,0), h1 = bfc(v.y,0), h2 = bfc(v.z,0), h3 = bfc(v.w,0);
        unsigned short l0 = bfc(v.x,1), l1 = bfc(v.y,1), l2 = bfc(v.z,1), l3 = bfc(v.w,1);
        u64 hq = (u64)h0 | ((u64)h1<<16) | ((u64)h2<<32) | ((u64)h3<<48);
        u64 lq = (u64)l0 | ((u64)l1<<16) | ((u64)l2<<32) | ((u64)l3<<48);
        int c = n0 >> 3;
        uint32_t off = (uint32_t)(k*128 + ((c ^ (k & 7)) << 4) + (n0 & 7)*2);
        *(u64*)(&sB[0][off]) = hq;
        *(u64*)(&sB[1][off]) = lq;
    }
    __syncthreads();

    uint32_t sb0 = smem_u32(sB[0]);
    uint32_t sb1 = smem_u32(sB[1]);
    int wid = tid >> 5, lane = tid & 31;
    int wm = wid & 3, wn = wid >> 2;
    int gid = lane >> 2, tig = lane & 3;
    int l16 = lane & 15;

    float acc[2][4][4];
#pragma unroll
    for (int m = 0; m < 2; m++)
#pragma unroll
        for (int n = 0; n < 4; n++)
#pragma unroll
            for (int q = 0; q < 4; q++) acc[m][n][q] = 0.f;

#pragma unroll
    for (int ks = 0; ks < 8; ks++){
        uint4 ah[2], al[2];
        ah[0] = g_wfrag[0][mt][wm*2 + 0][ks][lane];
        ah[1] = g_wfrag[0][mt][wm*2 + 1][ks][lane];
        al[0] = g_wfrag[1][mt][wm*2 + 0][ks][lane];
        al[1] = g_wfrag[1][mt][wm*2 + 1][ks][lane];
        uint32_t bh[4][2], bl[4][2];
        int krow = ks*16 + l16;
        uint32_t rowoff = (uint32_t)(krow * 128);
#pragma unroll
        for (int nn = 0; nn < 4; nn++){
            int c = wn*4 + nn;
            uint32_t off = rowoff + (uint32_t)(((c ^ (krow & 7)) << 4));
            ldm_x2_t(bh[nn][0], bh[nn][1], sb0 + off);
            ldm_x2_t(bl[nn][0], bl[nn][1], sb1 + off);
        }
#pragma unroll
        for (int mm = 0; mm < 2; mm++)
#pragma unroll
            for (int nn = 0; nn < 4; nn++){
                mma_bf16(acc[mm][nn], ah[mm], bh[nn]);
                mma_bf16(acc[mm][nn], ah[mm], bl[nn]);
                mma_bf16(acc[mm][nn], al[mm], bh[nn]);
            }
    }

    float* cb = C + ((size_t)b*384 + mt*128) * NTOT + n0blk;
#pragma unroll
    for (int mm = 0; mm < 2; mm++)
#pragma unroll
        for (int nn = 0; nn < 4; nn++){
            int row0 = wm*32 + mm*16 + gid;
            int col0 = wn*32 + nn*8 + 2*tig;
            *(float2*)(cb + (size_t)row0*NTOT + col0)     = make_float2(acc[mm][nn][0], acc[mm][nn][1]);
            *(float2*)(cb + (size_t)(row0+8)*NTOT + col0) = make_float2(acc[mm][nn][2], acc[mm][nn][3]);
        }
}

// proj GEMM (FFMA2): C[M,N] = W[M,128] @ X[128,N]
__global__ void __launch_bounds__(256, 2) k_gemm(const u64* __restrict__ w2,
                                                 const float* __restrict__ X,
                                                 float* __restrict__ C, int M){
    __shared__ u64 ws[2][16][128];
    __shared__ u64 xs[2][16][64];

    int tid = threadIdx.x;
    int b = blockIdx.z;
    int obase = blockIdx.y * 128;
    int nbase = blockIdx.x * 128;
    const float* x = X + (size_t)b * 128 * NTOT;
    float* c = C + (size_t)b * M * NTOT;
    int to8 = (tid >> 4) * 8;
    int tn4 = (tid & 15) * 4;

    auto load_chunk = [&](int kc, int buf){
#pragma unroll
        for (int t = 0; t < 4; t++){
            int e = t * 256 + tid;
            int k = e >> 6;
            int o = (2 * e) & 127;
            cp_async16(&ws[buf][k][o], w2 + (size_t)(kc*16 + k) * M + obase + o);
        }
#pragma unroll
        for (int t = 0; t < 2; t++){
            int e = t * 256 + tid;
            int k = e >> 5;
            int p = (2 * e) & 63;
            cp_async16(&xs[buf][k][p], x + (size_t)(kc*16 + k) * NTOT + nbase + 2*p);
        }
        cp_commit();
    };

    u64 acc[8][4];
#pragma unroll
    for (int o = 0; o < 8; o++)
#pragma unroll
        for (int p = 0; p < 4; p++) acc[o][p] = 0ULL;

    load_chunk(0, 0);
    cp_wait0(); __syncthreads();

    for (int kc = 0; kc < 8; kc++){
        int buf = kc & 1;
        if (kc < 7) load_chunk(kc + 1, buf ^ 1);
#pragma unroll
        for (int k = 0; k < 16; k++){
            u64 wv[8], xv[4];
#pragma unroll
            for (int j = 0; j < 4; j++){
                ulonglong2 t = *(const ulonglong2*)&ws[buf][k][to8 + 2*j];
                wv[2*j] = t.x; wv[2*j+1] = t.y;
            }
            {
                ulonglong2 t0 = *(const ulonglong2*)&xs[buf][k][tn4];
                ulonglong2 t1 = *(const ulonglong2*)&xs[buf][k][tn4 + 2];
                xv[0] = t0.x; xv[1] = t0.y; xv[2] = t1.x; xv[3] = t1.y;
            }
#pragma unroll
            for (int o = 0; o < 8; o++)
#pragma unroll
                for (int p = 0; p < 4; p++)
                    fma2(acc[o][p], wv[o], xv[p]);
        }
        if (kc < 7){ cp_wait0(); __syncthreads(); }
    }

#pragma unroll
    for (int o = 0; o < 8; o++){
        float2 f0 = unpack2(acc[o][0]), f1 = unpack2(acc[o][1]);
        float2 f2 = unpack2(acc[o][2]), f3 = unpack2(acc[o][3]);
        float* dst = c + (size_t)(obase + to8 + o) * NTOT + nbase + (tid & 15) * 8;
        *(float4*)(dst)     = make_float4(f0.x, f0.y, f1.x, f1.y);
        *(float4*)(dst + 4) = make_float4(f2.x, f2.y, f3.x, f3.y);
    }
}

// fused dwconv3x3 + sa gate + reductions + v write
__global__ void __launch_bounds__(256) k2_dw(const float* __restrict__ qkv_dw_w){
    int tid = threadIdx.x;
    int r = blockIdx.x, h = blockIdx.y, b = blockIdx.z;
    int g = tid >> 6, t = tid & 63;
    __shared__ __align__(16) float qs[16][268];
    __shared__ __align__(16) float ks[16][268];
    __shared__ float sdw[48][9];
    __shared__ __align__(16) float s_sa[256];
    __shared__ float s_ssq_q[16], s_ssq_k[16], s_vsum[16];

    if (tid < 64)
        *(float4*)(s_sa + 4*tid) = *(const float4*)(g_sa + (size_t)b*NTOT + r*256 + 4*tid);
    for (int idx = tid; idx < 432; idx += 256){
        int lc = idx / 9, j = idx % 9;
        int ch = (lc < 16) ? (h*16 + lc) : (lc < 32 ? (128 + h*16 + (lc-16)) : (256 + h*16 + (lc-32)));
        sdw[lc][j] = qkv_dw_w[ch*9 + j];
    }
    if (tid < 16){ s_ssq_q[tid] = 0.f; s_ssq_k[tid] = 0.f; s_vsum[tid] = 0.f; }
    __syncthreads();

    float4 sa4 = *(const float4*)(s_sa + 4*t);
    int lane = tid & 31;

    for (int lc0 = 0; lc0 < 48; lc0 += 4){
        int lc = lc0 + g;
        int ch = (lc < 16) ? (h*16 + lc) : (lc < 32 ? (128 + h*16 + (lc-16)) : (256 + h*16 + (lc-32)));
        const float* base = g_qkv1 + ((size_t)b*384 + ch) * NTOT;
        float4 v = conv3x4(base, r, t, sdw[lc]);
        if (lc < 16){
            v.x *= sa4.x; v.y *= sa4.y; v.z *= sa4.z; v.w *= sa4.w;
            *(float4*)&qs[lc][4*t] = v;
            float sq = v.x*v.x + v.y*v.y + v.z*v.z + v.w*v.w;
#pragma unroll
            for (int o = 16; o; o >>= 1) sq += __shfl_down_sync(0xffffffffu, sq, o);
            if (lane == 0) atomicAdd(&s_ssq_q[lc], sq);
        } else if (lc < 32){
            *(float4*)&ks[lc-16][4*t] = v;
            float sq = v.x*v.x + v.y*v.y + v.z*v.z + v.w*v.w;
#pragma unroll
            for (int o = 16; o; o >>= 1) sq += __shfl_down_sync(0xffffffffu, sq, o);
            if (lane == 0) atomicAdd(&s_ssq_k[lc-16], sq);
        } else {
            *(float4*)(g_v2 + ((size_t)b*128 + h*16 + (lc-32)) * NTOT + r*256 + 4*t) = v;
            float sv = v.x + v.y + v.z + v.w;
#pragma unroll
            for (int o = 16; o; o >>= 1) sv += __shfl_down_sync(0xffffffffu, sv, o);
            if (lane == 0) atomicAdd(&s_vsum[lc-32], sv);
        }
    }
    __syncthreads();

    int c = tid >> 4, d = tid & 15;
    float s = 0.f;
#pragma unroll 8
    for (int i = 0; i < 64; i++){
        float4 qv = *(const float4*)&qs[c][4*i];
        float4 kv = *(const float4*)&ks[d][4*i];
        s += qv.x*kv.x + qv.y*kv.y + qv.z*kv.z + qv.w*kv.w;
    }
    atomicAdd(&g_S[((b*8 + h)*16 + c)*16 + d], s);

    if (tid < 16){
        atomicAdd(&g_ssq_q[b*128 + h*16 + tid], s_ssq_q[tid]);
        atomicAdd(&g_ssq_k[b*128 + h*16 + tid], s_ssq_k[tid]);
        atomicAdd(&g_sumv [b*128 + h*16 + tid], s_vsum[tid]);
    }
}

// softmax + spectral MLP (one block, 256 threads)
__global__ void k4_small(const float* __restrict__ sp_w1, const float* __restrict__ sp_w2,
                         const float* __restrict__ sp_w3, const float* __restrict__ temp){
    __shared__ float pooled[2][128];
    __shared__ float t1s[2][16], t2s[2][16];
    int t = threadIdx.x;
    int b = t >> 7, row = t & 127, h = row >> 4, c = row & 15;

    float nq = fmaxf(sqrtf(g_ssq_q[b*128 + row]), 1e-12f);
    float tmp = temp[h];
    float logits[16];
    float mx = -1e30f;
#pragma unroll
    for (int d = 0; d < 16; d++){
        float nk = fmaxf(sqrtf(g_ssq_k[b*128 + h*16 + d]), 1e-12f);
        float L = g_S[((b*8 + h)*16 + c)*16 + d] / (nq * nk) * tmp;
        logits[d] = L; mx = fmaxf(mx, L);
    }
    float se = 0.f;
#pragma unroll
    for (int d = 0; d < 16; d++){ float e = expf(logits[d] - mx); logits[d] = e; se += e; }
    float inv = 1.f / se;
    float pool = 0.f;
#pragma unroll
    for (int d = 0; d < 16; d++){
        float a = logits[d] * inv;
        g_attn[b*2048 + (h*16 + c)*16 + d] = a;
        pool += a * g_sumv[b*128 + h*16 + d];
    }
    pooled[b][row] = pool * (1.f / 65536.f);
    __syncthreads();
    if (t < 32){
        int bb = t >> 4, j = t & 15;
        float s = 0.f;
        for (int c2 = 0; c2 < 128; c2++) s += sp_w1[j*128 + c2] * pooled[bb][c2];
        t1s[bb][j] = gelu_exact(s);
    }
    __syncthreads();
    if (t < 32){
        int bb = t >> 4, j = t & 15;
        float s = 0.f;
#pragma unroll
        for (int i = 0; i < 16; i++) s += sp_w2[j*16 + i] * t1s[bb][i];
        t2s[bb][j] = gelu_exact(s);
    }
    __syncthreads();
    {
        int bb = t >> 7, ch = t & 127;
        float s = 0.f;
#pragma unroll
        for (int j = 0; j < 16; j++) s += sp_w3[ch*16 + j] * t2s[bb][j];
        g_spec[bb*128 + ch] = 1.f / (1.f + expf(-s));
    }
}

// z = blockdiag(attn) @ v + spec * dwconv3x3(y); v tile staged in smem per head
__global__ void __launch_bounds__(256) k5a_z(const float* __restrict__ y,
                                             const float* __restrict__ dw_w){
    int tid = threadIdx.x;
    int r = blockIdx.x, b = blockIdx.y;
    int g = tid >> 6, t = tid & 63;
    __shared__ float s_attn[2048];
    __shared__ float s_spec[128];
    __shared__ float s_dw[128][9];
    __shared__ __align__(16) float sv[16][256];
    for (int i = tid; i < 2048; i += 256) s_attn[i] = g_attn[b*2048 + i];
    for (int i = tid; i < 1152; i += 256) (&s_dw[0][0])[i] = dw_w[i];
    if (tid < 128) s_spec[tid] = g_spec[b*128 + tid];
    __syncthreads();

    for (int h = 0; h < 8; h++){
        for (int i = tid; i < 1024; i += 256){
            int d = i >> 6, p = i & 63;
            *(float4*)&sv[d][4*p] =
                *(const float4*)(g_v2 + ((size_t)b*128 + h*16 + d) * NTOT + r*256 + 4*p);
        }
        __syncthreads();
#pragma unroll
        for (int cc = 0; cc < 4; cc++){
            int c = cc*4 + g;
            int ch = h*16 + c;
            const float* ybase = y + ((size_t)b*128 + ch) * NTOT;
            float4 z = conv3x4(ybase, r, t, s_dw[ch]);
            float sp = s_spec[ch];
            z.x *= sp; z.y *= sp; z.z *= sp; z.w *= sp;
            const float* arow = &s_attn[ch * 16];
#pragma unroll
            for (int d = 0; d < 16; d++){
                float a = arow[d];
                float4 vd = *(const float4*)&sv[d][4*t];
                z.x += a*vd.x; z.y += a*vd.y; z.z += a*vd.z; z.w += a*vd.w;
            }
            *(float4*)(g_z + ((size_t)b*128 + ch) * NTOT + r*256 + 4*t) = z;
        }
        __syncthreads();
    }
}

extern "C" void kernel_launch(void* const* d_in, const int* in_sizes, int n_in,
                              void* d_out, int out_size){
    const float* x        = (const float*)d_in[0];
    const float* y        = (const float*)d_in[1];
    const float* qkv_w    = (const float*)d_in[2];
    const float* qkv_dw_w = (const float*)d_in[3];
    const float* proj_w   = (const float*)d_in[4];
    const float* sa_w1    = (const float*)d_in[5];
    const float* sa_w2    = (const float*)d_in[6];
    const float* sa_w3    = (const float*)d_in[7];
    const float* sp_w1    = (const float*)d_in[8];
    const float* sp_w2    = (const float*)d_in[9];
    const float* sp_w3    = (const float*)d_in[10];
    const float* dw_w     = (const float*)d_in[11];
    const float* temp     = (const float*)d_in[12];
    float* out = (float*)d_out;

    u64 *wp2;
    float *qkv1, *z;
    cudaGetSymbolAddress((void**)&wp2,  g_wp2);
    cudaGetSymbolAddress((void**)&qkv1, g_qkv1);
    cudaGetSymbolAddress((void**)&z,    g_z);

    k_prep<<<131, 256>>>(qkv_w, proj_w);
    k_sa<<<dim3(128, 2), 256>>>(y, sa_w1, sa_w2, sa_w3);
    k_qkv_mma<<<dim3(1024, 3, 2), 256>>>(x, qkv1);
    k2_dw<<<dim3(256, 8, 2), 256>>>(qkv_dw_w);
    k4_small<<<1, 256>>>(sp_w1, sp_w2, sp_w3, temp);
    k5a_z<<<dim3(256, 2), 256>>>(y, dw_w);
    k_gemm<<<dim3(512, 1, 2), 256>>>(wp2, z, out, 128);
}

// round 14
// speedup vs baseline: 1.6247x; 1.1482x over previous
#include <cuda_runtime.h>
#include <cuda_bf16.h>
#include <cstdint>

typedef unsigned long long u64;
#define NTOT 65536
#define BATCH 2

__device__ __align__(16) float g_qkv1[(size_t)BATCH*384*NTOT];
__device__ __align__(16) float g_sa  [(size_t)BATCH*NTOT];
__device__ __align__(16) float g_v2  [(size_t)BATCH*128*NTOT];
__device__ __align__(16) float g_z   [(size_t)BATCH*128*NTOT];
__device__ float g_S[4096];
__device__ float g_ssq_q[256];
__device__ float g_ssq_k[256];
__device__ float g_sumv[256];
__device__ float g_attn[4096];
__device__ float g_spec[256];
// mma A-fragments: [hi/lo][mtile][m16-tile][kstep][lane] = {a0,a1,a2,a3}
__device__ __align__(16) uint4 g_wfrag_q[2][3][8][8][32];
__device__ __align__(16) uint4 g_wfrag_p[2][1][8][8][32];

__device__ __forceinline__ float gelu_exact(float x){
    return 0.5f * x * (1.0f + erff(x * 0.70710678118654752f));
}
__device__ __forceinline__ uint32_t smem_u32(const void* p){
    uint32_t a;
    asm("{ .reg .u64 t; cvta.to.shared.u64 t, %1; cvt.u32.u64 %0, t; }" : "=r"(a) : "l"(p));
    return a;
}
__device__ __forceinline__ void mma_bf16(float (&c)[4], const uint4& a, const uint32_t* b){
    asm volatile("mma.sync.aligned.m16n8k16.row.col.f32.bf16.bf16.f32 "
        "{%0,%1,%2,%3}, {%4,%5,%6,%7}, {%8,%9}, {%0,%1,%2,%3};"
        : "+f"(c[0]), "+f"(c[1]), "+f"(c[2]), "+f"(c[3])
        : "r"(a.x), "r"(a.y), "r"(a.z), "r"(a.w), "r"(b[0]), "r"(b[1]));
}
__device__ __forceinline__ void ldm_x2_t(uint32_t& r0, uint32_t& r1, uint32_t addr){
    asm volatile("ldmatrix.sync.aligned.m8n8.x2.trans.shared.b16 {%0,%1}, [%2];"
        : "=r"(r0), "=r"(r1) : "r"(addr));
}
__device__ __forceinline__ unsigned short bfc(float v, int lo){
    __nv_bfloat16 h = __float2bfloat16(v);
    if (lo){ float res = v - __bfloat162float(h); h = __float2bfloat16(res); }
    return __bfloat16_as_ushort(h);
}

// ---- 4-wide single-row stencil over full 256-col row (t in [0,64)) ----
__device__ __forceinline__ void conv_acc4(float4& o, int valid, const float* row, int t,
                                          float w0, float w1, float w2){
    if (!valid) return;
    float4 a = __ldg((const float4*)(row + 4*t));
    float lf = __shfl_up_sync(0xffffffffu, a.w, 1);
    float rt = __shfl_down_sync(0xffffffffu, a.x, 1);
    int lane = t & 31;
    if (lane == 0)  lf = (t == 32) ? __ldg(row + 127) : 0.f;
    if (lane == 31) rt = (t == 31) ? __ldg(row + 128) : 0.f;
    o.x += w0*lf  + w1*a.x + w2*a.y;
    o.y += w0*a.x + w1*a.y + w2*a.z;
    o.z += w0*a.y + w1*a.z + w2*a.w;
    o.w += w0*a.z + w1*a.w + w2*rt;
}
__device__ __forceinline__ float4 conv3x4(const float* base, int r, int t, const float* w){
    float4 o = make_float4(0.f, 0.f, 0.f, 0.f);
    conv_acc4(o, r > 0,   base + (size_t)(r-1)*256, t, w[0], w[1], w[2]);
    conv_acc4(o, 1,       base + (size_t)r*256,     t, w[3], w[4], w[5]);
    conv_acc4(o, r < 255, base + (size_t)(r+1)*256, t, w[6], w[7], w[8]);
    return o;
}

// zeros + mma fragments for qkv_w (3 mtiles) and proj_w (1 mtile)
__global__ void k_prep(const float* __restrict__ qkv_w, const float* __restrict__ proj_w){
    int idx = blockIdx.x * 256 + threadIdx.x;
    if (idx < 4864){
        if (idx < 4096) g_S[idx] = 0.f;
        else if (idx < 4352) g_ssq_q[idx-4096] = 0.f;
        else if (idx < 4608) g_ssq_k[idx-4352] = 0.f;
        else g_sumv[idx-4608] = 0.f;
    } else if (idx < 17152){
        int t = idx - 4864;           // 0..12287  qkv fragments
        int lane = t & 31; t >>= 5;
        int ks = t & 7;   t >>= 3;
        int mm = t & 7;   t >>= 3;
        int mt = t % 3;
        int hl = t / 3;
        int gid = lane >> 2, tig = lane & 3;
        int row0 = mt*128 + mm*16 + gid;
        int k0 = ks*16 + 2*tig;
        uint32_t a0 = (uint32_t)bfc(qkv_w[row0*128 + k0], hl)
                    | ((uint32_t)bfc(qkv_w[row0*128 + k0 + 1], hl) << 16);
        uint32_t a1 = (uint32_t)bfc(qkv_w[(row0+8)*128 + k0], hl)
                    | ((uint32_t)bfc(qkv_w[(row0+8)*128 + k0 + 1], hl) << 16);
        uint32_t a2 = (uint32_t)bfc(qkv_w[row0*128 + k0 + 8], hl)
                    | ((uint32_t)bfc(qkv_w[row0*128 + k0 + 9], hl) << 16);
        uint32_t a3 = (uint32_t)bfc(qkv_w[(row0+8)*128 + k0 + 8], hl)
                    | ((uint32_t)bfc(qkv_w[(row0+8)*128 + k0 + 9], hl) << 16);
        g_wfrag_q[hl][mt][mm][ks][lane] = make_uint4(a0, a1, a2, a3);
    } else {
        int t = idx - 17152;          // 0..4095  proj fragments
        int lane = t & 31; t >>= 5;
        int ks = t & 7;   t >>= 3;
        int mm = t & 7;   t >>= 3;
        int hl = t;                   // 0..1
        int gid = lane >> 2, tig = lane & 3;
        int row0 = mm*16 + gid;
        int k0 = ks*16 + 2*tig;
        uint32_t a0 = (uint32_t)bfc(proj_w[row0*128 + k0], hl)
                    | ((uint32_t)bfc(proj_w[row0*128 + k0 + 1], hl) << 16);
        uint32_t a1 = (uint32_t)bfc(proj_w[(row0+8)*128 + k0], hl)
                    | ((uint32_t)bfc(proj_w[(row0+8)*128 + k0 + 1], hl) << 16);
        uint32_t a2 = (uint32_t)bfc(proj_w[row0*128 + k0 + 8], hl)
                    | ((uint32_t)bfc(proj_w[row0*128 + k0 + 9], hl) << 16);
        uint32_t a3 = (uint32_t)bfc(proj_w[(row0+8)*128 + k0 + 8], hl)
                    | ((uint32_t)bfc(proj_w[(row0+8)*128 + k0 + 9], hl) << 16);
        g_wfrag_p[hl][0][mm][ks][lane] = make_uint4(a0, a1, a2, a3);
    }
}

// spatial gate: 2 px per thread, 256 blocks total
__global__ void __launch_bounds__(256) k_sa(const float* __restrict__ y,
                                            const float* __restrict__ w1,
                                            const float* __restrict__ w2,
                                            const float* __restrict__ w3){
    __shared__ float sW1[128][16];
    __shared__ float sW2[16][16];
    __shared__ float sW3[16];
    int tid = threadIdx.x;
    int b = blockIdx.y;
    for (int i = tid; i < 2048; i += 256){ int c = i >> 4, j = i & 15; sW1[c][j] = w1[j*128 + c]; }
    (&sW2[0][0])[tid] = w2[tid];
    if (tid < 16) sW3[tid] = w3[tid];
    __syncthreads();

    int n0 = (blockIdx.x * 256 + tid) * 2;
    float acc[2][16];
#pragma unroll
    for (int p = 0; p < 2; p++)
#pragma unroll
        for (int j = 0; j < 16; j++) acc[p][j] = 0.f;

    const float* yb = y + (size_t)b * 128 * NTOT + n0;
#pragma unroll 4
    for (int c = 0; c < 128; c++){
        float2 yv = *(const float2*)(yb + (size_t)c * NTOT);
#pragma unroll
        for (int j = 0; j < 16; j++){
            float w = sW1[c][j];
            acc[0][j] += w * yv.x; acc[1][j] += w * yv.y;
        }
    }
    float out[2];
#pragma unroll
    for (int p = 0; p < 2; p++){
        float t2[16];
#pragma unroll
        for (int i = 0; i < 16; i++){
            float s = 0.f;
#pragma unroll
            for (int j = 0; j < 16; j++) s += sW2[i][j] * fmaxf(acc[p][j], 0.f);
            t2[i] = fmaxf(s, 0.f);
        }
        float s3 = 0.f;
#pragma unroll
        for (int j = 0; j < 16; j++) s3 += sW3[j] * t2[j];
        out[p] = 1.f / (1.f + expf(-s3));
    }
    *(float2*)(g_sa + (size_t)b * NTOT + n0) = make_float2(out[0], out[1]);
}

// ===== GEMM on tensor cores: C[MT*128, N] = W @ X, bf16-split mma.sync =====
// block: 128M x 64N tile; 8 warps = 4M x 2N; warp tile 32M x 32N.
// wf layout: [hi/lo][MT][8][8][32] flattened.
__global__ void __launch_bounds__(256) k_mma(const float* __restrict__ X,
                                             float* __restrict__ C,
                                             const uint4* __restrict__ wf, int MT){
    __shared__ __align__(16) unsigned char sB[2][16384];  // bf16 hi/lo X tile [128k][64n], swizzled
    int tid = threadIdx.x;
    int nb = blockIdx.x, mt = blockIdx.y, b = blockIdx.z;
    int n0blk = nb * 64;
    const float* x = X + (size_t)b * 128 * NTOT;

    // convert X tile f32 -> bf16 hi/lo into swizzled smem
#pragma unroll
    for (int j = 0; j < 8; j++){
        int i = j*256 + tid;
        int k = i >> 4;             // 0..127
        int n0 = (i & 15) * 4;      // 0..60
        float4 v = *(const float4*)(x + (size_t)k*NTOT + n0blk + n0);
        unsigned short h0 = bfc(v.x,0), h1 = bfc(v.y,0), h2 = bfc(v.z,0), h3 = bfc(v.w,0);
        unsigned short l0 = bfc(v.x,1), l1 = bfc(v.y,1), l2 = bfc(v.z,1), l3 = bfc(v.w,1);
        u64 hq = (u64)h0 | ((u64)h1<<16) | ((u64)h2<<32) | ((u64)h3<<48);
        u64 lq = (u64)l0 | ((u64)l1<<16) | ((u64)l2<<32) | ((u64)l3<<48);
        int c = n0 >> 3;
        uint32_t off = (uint32_t)(k*128 + ((c ^ (k & 7)) << 4) + (n0 & 7)*2);
        *(u64*)(&sB[0][off]) = hq;
        *(u64*)(&sB[1][off]) = lq;
    }
    __syncthreads();

    uint32_t sb0 = smem_u32(sB[0]);
    uint32_t sb1 = smem_u32(sB[1]);
    int wid = tid >> 5, lane = tid & 31;
    int wm = wid & 3, wn = wid >> 2;
    int gid = lane >> 2, tig = lane & 3;
    int l16 = lane & 15;

    const uint4* wfh = wf + (((size_t)0*MT + mt)*8)*8*32;
    const uint4* wfl = wf + (((size_t)1*MT + mt)*8)*8*32;

    float acc[2][4][4];
#pragma unroll
    for (int m = 0; m < 2; m++)
#pragma unroll
        for (int n = 0; n < 4; n++)
#pragma unroll
            for (int q = 0; q < 4; q++) acc[m][n][q] = 0.f;

#pragma unroll
    for (int ks = 0; ks < 8; ks++){
        uint4 ah[2], al[2];
        ah[0] = wfh[((wm*2 + 0)*8 + ks)*32 + lane];
        ah[1] = wfh[((wm*2 + 1)*8 + ks)*32 + lane];
        al[0] = wfl[((wm*2 + 0)*8 + ks)*32 + lane];
        al[1] = wfl[((wm*2 + 1)*8 + ks)*32 + lane];
        uint32_t bh[4][2], bl[4][2];
        int krow = ks*16 + l16;
        uint32_t rowoff = (uint32_t)(krow * 128);
#pragma unroll
        for (int nn = 0; nn < 4; nn++){
            int c = wn*4 + nn;
            uint32_t off = rowoff + (uint32_t)(((c ^ (krow & 7)) << 4));
            ldm_x2_t(bh[nn][0], bh[nn][1], sb0 + off);
            ldm_x2_t(bl[nn][0], bl[nn][1], sb1 + off);
        }
#pragma unroll
        for (int mm = 0; mm < 2; mm++)
#pragma unroll
            for (int nn = 0; nn < 4; nn++){
                mma_bf16(acc[mm][nn], ah[mm], bh[nn]);
                mma_bf16(acc[mm][nn], ah[mm], bl[nn]);
                mma_bf16(acc[mm][nn], al[mm], bh[nn]);
            }
    }

    float* cb = C + ((size_t)(b*MT + mt) * 128) * NTOT + n0blk;
#pragma unroll
    for (int mm = 0; mm < 2; mm++)
#pragma unroll
        for (int nn = 0; nn < 4; nn++){
            int row0 = wm*32 + mm*16 + gid;
            int col0 = wn*32 + nn*8 + 2*tig;
            *(float2*)(cb + (size_t)row0*NTOT + col0)     = make_float2(acc[mm][nn][0], acc[mm][nn][1]);
            *(float2*)(cb + (size_t)(row0+8)*NTOT + col0) = make_float2(acc[mm][nn][2], acc[mm][nn][3]);
        }
}

// fused dwconv3x3 + sa gate + reductions + v write
__global__ void __launch_bounds__(256) k2_dw(const float* __restrict__ qkv_dw_w){
    int tid = threadIdx.x;
    int r = blockIdx.x, h = blockIdx.y, b = blockIdx.z;
    int g = tid >> 6, t = tid & 63;
    __shared__ __align__(16) float qs[16][268];
    __shared__ __align__(16) float ks[16][268];
    __shared__ float sdw[48][9];
    __shared__ __align__(16) float s_sa[256];
    __shared__ float s_ssq_q[16], s_ssq_k[16], s_vsum[16];

    if (tid < 64)
        *(float4*)(s_sa + 4*tid) = *(const float4*)(g_sa + (size_t)b*NTOT + r*256 + 4*tid);
    for (int idx = tid; idx < 432; idx += 256){
        int lc = idx / 9, j = idx % 9;
        int ch = (lc < 16) ? (h*16 + lc) : (lc < 32 ? (128 + h*16 + (lc-16)) : (256 + h*16 + (lc-32)));
        sdw[lc][j] = qkv_dw_w[ch*9 + j];
    }
    if (tid < 16){ s_ssq_q[tid] = 0.f; s_ssq_k[tid] = 0.f; s_vsum[tid] = 0.f; }
    __syncthreads();

    float4 sa4 = *(const float4*)(s_sa + 4*t);
    int lane = tid & 31;

    for (int lc0 = 0; lc0 < 48; lc0 += 4){
        int lc = lc0 + g;
        int ch = (lc < 16) ? (h*16 + lc) : (lc < 32 ? (128 + h*16 + (lc-16)) : (256 + h*16 + (lc-32)));
        const float* base = g_qkv1 + ((size_t)b*384 + ch) * NTOT;
        float4 v = conv3x4(base, r, t, sdw[lc]);
        if (lc < 16){
            v.x *= sa4.x; v.y *= sa4.y; v.z *= sa4.z; v.w *= sa4.w;
            *(float4*)&qs[lc][4*t] = v;
            float sq = v.x*v.x + v.y*v.y + v.z*v.z + v.w*v.w;
#pragma unroll
            for (int o = 16; o; o >>= 1) sq += __shfl_down_sync(0xffffffffu, sq, o);
            if (lane == 0) atomicAdd(&s_ssq_q[lc], sq);
        } else if (lc < 32){
            *(float4*)&ks[lc-16][4*t] = v;
            float sq = v.x*v.x + v.y*v.y + v.z*v.z + v.w*v.w;
#pragma unroll
            for (int o = 16; o; o >>= 1) sq += __shfl_down_sync(0xffffffffu, sq, o);
            if (lane == 0) atomicAdd(&s_ssq_k[lc-16], sq);
        } else {
            *(float4*)(g_v2 + ((size_t)b*128 + h*16 + (lc-32)) * NTOT + r*256 + 4*t) = v;
            float sv = v.x + v.y + v.z + v.w;
#pragma unroll
            for (int o = 16; o; o >>= 1) sv += __shfl_down_sync(0xffffffffu, sv, o);
            if (lane == 0) atomicAdd(&s_vsum[lc-32], sv);
        }
    }
    __syncthreads();

    int c = tid >> 4, d = tid & 15;
    float s = 0.f;
#pragma unroll 8
    for (int i = 0; i < 64; i++){
        float4 qv = *(const float4*)&qs[c][4*i];
        float4 kv = *(const float4*)&ks[d][4*i];
        s += qv.x*kv.x + qv.y*kv.y + qv.z*kv.z + qv.w*kv.w;
    }
    atomicAdd(&g_S[((b*8 + h)*16 + c)*16 + d], s);

    if (tid < 16){
        atomicAdd(&g_ssq_q[b*128 + h*16 + tid], s_ssq_q[tid]);
        atomicAdd(&g_ssq_k[b*128 + h*16 + tid], s_ssq_k[tid]);
        atomicAdd(&g_sumv [b*128 + h*16 + tid], s_vsum[tid]);
    }
}

// softmax + spectral MLP (one block, 256 threads)
__global__ void k4_small(const float* __restrict__ sp_w1, const float* __restrict__ sp_w2,
                         const float* __restrict__ sp_w3, const float* __restrict__ temp){
    __shared__ float pooled[2][128];
    __shared__ float t1s[2][16], t2s[2][16];
    int t = threadIdx.x;
    int b = t >> 7, row = t & 127, h = row >> 4, c = row & 15;

    float nq = fmaxf(sqrtf(g_ssq_q[b*128 + row]), 1e-12f);
    float tmp = temp[h];
    float logits[16];
    float mx = -1e30f;
#pragma unroll
    for (int d = 0; d < 16; d++){
        float nk = fmaxf(sqrtf(g_ssq_k[b*128 + h*16 + d]), 1e-12f);
        float L = g_S[((b*8 + h)*16 + c)*16 + d] / (nq * nk) * tmp;
        logits[d] = L; mx = fmaxf(mx, L);
    }
    float se = 0.f;
#pragma unroll
    for (int d = 0; d < 16; d++){ float e = expf(logits[d] - mx); logits[d] = e; se += e; }
    float inv = 1.f / se;
    float pool = 0.f;
#pragma unroll
    for (int d = 0; d < 16; d++){
        float a = logits[d] * inv;
        g_attn[b*2048 + (h*16 + c)*16 + d] = a;
        pool += a * g_sumv[b*128 + h*16 + d];
    }
    pooled[b][row] = pool * (1.f / 65536.f);
    __syncthreads();
    if (t < 32){
        int bb = t >> 4, j = t & 15;
        float s = 0.f;
        for (int c2 = 0; c2 < 128; c2++) s += sp_w1[j*128 + c2] * pooled[bb][c2];
        t1s[bb][j] = gelu_exact(s);
    }
    __syncthreads();
    if (t < 32){
        int bb = t >> 4, j = t & 15;
        float s = 0.f;
#pragma unroll
        for (int i = 0; i < 16; i++) s += sp_w2[j*16 + i] * t1s[bb][i];
        t2s[bb][j] = gelu_exact(s);
    }
    __syncthreads();
    {
        int bb = t >> 7, ch = t & 127;
        float s = 0.f;
#pragma unroll
        for (int j = 0; j < 16; j++) s += sp_w3[ch*16 + j] * t2s[bb][j];
        g_spec[bb*128 + ch] = 1.f / (1.f + expf(-s));
    }
}

// z = blockdiag(attn) @ v + spec * dwconv3x3(y); v tile staged in smem per head
__global__ void __launch_bounds__(256) k5a_z(const float* __restrict__ y,
                                             const float* __restrict__ dw_w){
    int tid = threadIdx.x;
    int r = blockIdx.x, b = blockIdx.y;
    int g = tid >> 6, t = tid & 63;
    __shared__ float s_attn[2048];
    __shared__ float s_spec[128];
    __shared__ float s_dw[128][9];
    __shared__ __align__(16) float sv[16][256];
    for (int i = tid; i < 2048; i += 256) s_attn[i] = g_attn[b*2048 + i];
    for (int i = tid; i < 1152; i += 256) (&s_dw[0][0])[i] = dw_w[i];
    if (tid < 128) s_spec[tid] = g_spec[b*128 + tid];
    __syncthreads();

    for (int h = 0; h < 8; h++){
        for (int i = tid; i < 1024; i += 256){
            int d = i >> 6, p = i & 63;
            *(float4*)&sv[d][4*p] =
                *(const float4*)(g_v2 + ((size_t)b*128 + h*16 + d) * NTOT + r*256 + 4*p);
        }
        __syncthreads();
#pragma unroll
        for (int cc = 0; cc < 4; cc++){
            int c = cc*4 + g;
            int ch = h*16 + c;
            const float* ybase = y + ((size_t)b*128 + ch) * NTOT;
            float4 z = conv3x4(ybase, r, t, s_dw[ch]);
            float sp = s_spec[ch];
            z.x *= sp; z.y *= sp; z.z *= sp; z.w *= sp;
            const float* arow = &s_attn[ch * 16];
#pragma unroll
            for (int d = 0; d < 16; d++){
                float a = arow[d];
                float4 vd = *(const float4*)&sv[d][4*t];
                z.x += a*vd.x; z.y += a*vd.y; z.z += a*vd.z; z.w += a*vd.w;
            }
            *(float4*)(g_z + ((size_t)b*128 + ch) * NTOT + r*256 + 4*t) = z;
        }
        __syncthreads();
    }
}

extern "C" void kernel_launch(void* const* d_in, const int* in_sizes, int n_in,
                              void* d_out, int out_size){
    const float* x        = (const float*)d_in[0];
    const float* y        = (const float*)d_in[1];
    const float* qkv_w    = (const float*)d_in[2];
    const float* qkv_dw_w = (const float*)d_in[3];
    const float* proj_w   = (const float*)d_in[4];
    const float* sa_w1    = (const float*)d_in[5];
    const float* sa_w2    = (const float*)d_in[6];
    const float* sa_w3    = (const float*)d_in[7];
    const float* sp_w1    = (const float*)d_in[8];
    const float* sp_w2    = (const float*)d_in[9];
    const float* sp_w3    = (const float*)d_in[10];
    const float* dw_w     = (const float*)d_in[11];
    const float* temp     = (const float*)d_in[12];
    float* out = (float*)d_out;

    float *qkv1, *z;
    uint4 *wfq, *wfp;
    cudaGetSymbolAddress((void**)&qkv1, g_qkv1);
    cudaGetSymbolAddress((void**)&z,    g_z);
    cudaGetSymbolAddress((void**)&wfq,  g_wfrag_q);
    cudaGetSymbolAddress((void**)&wfp,  g_wfrag_p);

    k_prep<<<83, 256>>>(qkv_w, proj_w);
    k_sa<<<dim3(128, 2), 256>>>(y, sa_w1, sa_w2, sa_w3);
    k_mma<<<dim3(1024, 3, 2), 256>>>(x, qkv1, wfq, 3);
    k2_dw<<<dim3(256, 8, 2), 256>>>(qkv_dw_w);
    k4_small<<<1, 256>>>(sp_w1, sp_w2, sp_w3, temp);
    k5a_z<<<dim3(256, 2), 256>>>(y, dw_w);
    k_mma<<<dim3(1024, 1, 2), 256>>>(z, out, wfp, 1);
}

// round 16
// speedup vs baseline: 1.8991x; 1.1689x over previous
#include <cuda_runtime.h>
#include <cuda_bf16.h>
#include <cstdint>

typedef unsigned long long u64;
#define NTOT 65536
#define BATCH 2

__device__ __align__(16) float g_qkv1[(size_t)BATCH*384*NTOT];
__device__ __align__(16) float g_sa  [(size_t)BATCH*NTOT];
__device__ __align__(16) float g_v2  [(size_t)BATCH*128*NTOT];
__device__ __align__(16) float g_z   [(size_t)BATCH*128*NTOT];
__device__ float g_S[4096];
__device__ float g_ssq_q[256];
__device__ float g_ssq_k[256];
__device__ float g_sumv[256];
__device__ float g_attn[4096];
__device__ float g_spec[256];
// mma A-fragments: [hi/lo][mtile][m16-tile][kstep][lane] = {a0,a1,a2,a3}
__device__ __align__(16) uint4 g_wfrag_q[2][3][8][8][32];
__device__ __align__(16) uint4 g_wfrag_p[2][1][8][8][32];

__device__ __forceinline__ float gelu_exact(float x){
    return 0.5f * x * (1.0f + erff(x * 0.70710678118654752f));
}
__device__ __forceinline__ uint32_t smem_u32(const void* p){
    uint32_t a;
    asm("{ .reg .u64 t; cvta.to.shared.u64 t, %1; cvt.u32.u64 %0, t; }" : "=r"(a) : "l"(p));
    return a;
}
__device__ __forceinline__ void mma_bf16(float (&c)[4], const uint4& a, const uint32_t* b){
    asm volatile("mma.sync.aligned.m16n8k16.row.col.f32.bf16.bf16.f32 "
        "{%0,%1,%2,%3}, {%4,%5,%6,%7}, {%8,%9}, {%0,%1,%2,%3};"
        : "+f"(c[0]), "+f"(c[1]), "+f"(c[2]), "+f"(c[3])
        : "r"(a.x), "r"(a.y), "r"(a.z), "r"(a.w), "r"(b[0]), "r"(b[1]));
}
__device__ __forceinline__ void ldm_x2_t(uint32_t& r0, uint32_t& r1, uint32_t addr){
    asm volatile("ldmatrix.sync.aligned.m8n8.x2.trans.shared.b16 {%0,%1}, [%2];"
        : "=r"(r0), "=r"(r1) : "r"(addr));
}
__device__ __forceinline__ unsigned short bfc(float v, int lo){
    __nv_bfloat16 h = __float2bfloat16(v);
    if (lo){ float res = v - __bfloat162float(h); h = __float2bfloat16(res); }
    return __bfloat16_as_ushort(h);
}

// ---- 4-wide single-row stencil over full 256-col row (t in [0,64)) ----
__device__ __forceinline__ void conv_acc4(float4& o, int valid, const float* row, int t,
                                          float w0, float w1, float w2){
    if (!valid) return;
    float4 a = __ldg((const float4*)(row + 4*t));
    float lf = __shfl_up_sync(0xffffffffu, a.w, 1);
    float rt = __shfl_down_sync(0xffffffffu, a.x, 1);
    int lane = t & 31;
    if (lane == 0)  lf = (t == 32) ? __ldg(row + 127) : 0.f;
    if (lane == 31) rt = (t == 31) ? __ldg(row + 128) : 0.f;
    o.x += w0*lf  + w1*a.x + w2*a.y;
    o.y += w0*a.x + w1*a.y + w2*a.z;
    o.z += w0*a.y + w1*a.z + w2*a.w;
    o.w += w0*a.z + w1*a.w + w2*rt;
}
__device__ __forceinline__ float4 conv3x4(const float* base, int r, int t, const float* w){
    float4 o = make_float4(0.f, 0.f, 0.f, 0.f);
    conv_acc4(o, r > 0,   base + (size_t)(r-1)*256, t, w[0], w[1], w[2]);
    conv_acc4(o, 1,       base + (size_t)r*256,     t, w[3], w[4], w[5]);
    conv_acc4(o, r < 255, base + (size_t)(r+1)*256, t, w[6], w[7], w[8]);
    return o;
}

// zeros + mma fragments for qkv_w (3 mtiles) and proj_w (1 mtile)
__global__ void k_prep(const float* __restrict__ qkv_w, const float* __restrict__ proj_w){
    int idx = blockIdx.x * 256 + threadIdx.x;
    if (idx < 4864){
        if (idx < 4096) g_S[idx] = 0.f;
        else if (idx < 4352) g_ssq_q[idx-4096] = 0.f;
        else if (idx < 4608) g_ssq_k[idx-4352] = 0.f;
        else g_sumv[idx-4608] = 0.f;
    } else if (idx < 17152){
        int t = idx - 4864;
        int lane = t & 31; t >>= 5;
        int ks = t & 7;   t >>= 3;
        int mm = t & 7;   t >>= 3;
        int mt = t % 3;
        int hl = t / 3;
        int gid = lane >> 2, tig = lane & 3;
        int row0 = mt*128 + mm*16 + gid;
        int k0 = ks*16 + 2*tig;
        uint32_t a0 = (uint32_t)bfc(qkv_w[row0*128 + k0], hl)
                    | ((uint32_t)bfc(qkv_w[row0*128 + k0 + 1], hl) << 16);
        uint32_t a1 = (uint32_t)bfc(qkv_w[(row0+8)*128 + k0], hl)
                    | ((uint32_t)bfc(qkv_w[(row0+8)*128 + k0 + 1], hl) << 16);
        uint32_t a2 = (uint32_t)bfc(qkv_w[row0*128 + k0 + 8], hl)
                    | ((uint32_t)bfc(qkv_w[row0*128 + k0 + 9], hl) << 16);
        uint32_t a3 = (uint32_t)bfc(qkv_w[(row0+8)*128 + k0 + 8], hl)
                    | ((uint32_t)bfc(qkv_w[(row0+8)*128 + k0 + 9], hl) << 16);
        g_wfrag_q[hl][mt][mm][ks][lane] = make_uint4(a0, a1, a2, a3);
    } else {
        int t = idx - 17152;
        int lane = t & 31; t >>= 5;
        int ks = t & 7;   t >>= 3;
        int mm = t & 7;   t >>= 3;
        int hl = t;
        int gid = lane >> 2, tig = lane & 3;
        int row0 = mm*16 + gid;
        int k0 = ks*16 + 2*tig;
        uint32_t a0 = (uint32_t)bfc(proj_w[row0*128 + k0], hl)
                    | ((uint32_t)bfc(proj_w[row0*128 + k0 + 1], hl) << 16);
        uint32_t a1 = (uint32_t)bfc(proj_w[(row0+8)*128 + k0], hl)
                    | ((uint32_t)bfc(proj_w[(row0+8)*128 + k0 + 1], hl) << 16);
        uint32_t a2 = (uint32_t)bfc(proj_w[row0*128 + k0 + 8], hl)
                    | ((uint32_t)bfc(proj_w[row0*128 + k0 + 9], hl) << 16);
        uint32_t a3 = (uint32_t)bfc(proj_w[(row0+8)*128 + k0 + 8], hl)
                    | ((uint32_t)bfc(proj_w[(row0+8)*128 + k0 + 9], hl) << 16);
        g_wfrag_p[hl][0][mm][ks][lane] = make_uint4(a0, a1, a2, a3);
    }
}

// spatial gate: 2 px per thread, 256 blocks total
__global__ void __launch_bounds__(256) k_sa(const float* __restrict__ y,
                                            const float* __restrict__ w1,
                                            const float* __restrict__ w2,
                                            const float* __restrict__ w3){
    __shared__ float sW1[128][16];
    __shared__ float sW2[16][16];
    __shared__ float sW3[16];
    int tid = threadIdx.x;
    int b = blockIdx.y;
    for (int i = tid; i < 2048; i += 256){ int c = i >> 4, j = i & 15; sW1[c][j] = w1[j*128 + c]; }
    (&sW2[0][0])[tid] = w2[tid];
    if (tid < 16) sW3[tid] = w3[tid];
    __syncthreads();

    int n0 = (blockIdx.x * 256 + tid) * 2;
    float acc[2][16];
#pragma unroll
    for (int p = 0; p < 2; p++)
#pragma unroll
        for (int j = 0; j < 16; j++) acc[p][j] = 0.f;

    const float* yb = y + (size_t)b * 128 * NTOT + n0;
#pragma unroll 4
    for (int c = 0; c < 128; c++){
        float2 yv = *(const float2*)(yb + (size_t)c * NTOT);
#pragma unroll
        for (int j = 0; j < 16; j++){
            float w = sW1[c][j];
            acc[0][j] += w * yv.x; acc[1][j] += w * yv.y;
        }
    }
    float out[2];
#pragma unroll
    for (int p = 0; p < 2; p++){
        float t2[16];
#pragma unroll
        for (int i = 0; i < 16; i++){
            float s = 0.f;
#pragma unroll
            for (int j = 0; j < 16; j++) s += sW2[i][j] * fmaxf(acc[p][j], 0.f);
            t2[i] = fmaxf(s, 0.f);
        }
        float s3 = 0.f;
#pragma unroll
        for (int j = 0; j < 16; j++) s3 += sW3[j] * t2[j];
        out[p] = 1.f / (1.f + expf(-s3));
    }
    *(float2*)(g_sa + (size_t)b * NTOT + n0) = make_float2(out[0], out[1]);
}

// ===== GEMM on tensor cores: C[MT*128, N] = W @ X, bf16-split mma.sync =====
__global__ void __launch_bounds__(256) k_mma(const float* __restrict__ X,
                                             float* __restrict__ C,
                                             const uint4* __restrict__ wf, int MT){
    __shared__ __align__(16) unsigned char sB[2][16384];
    int tid = threadIdx.x;
    int nb = blockIdx.x, mt = blockIdx.y, b = blockIdx.z;
    int n0blk = nb * 64;
    const float* x = X + (size_t)b * 128 * NTOT;

#pragma unroll
    for (int j = 0; j < 8; j++){
        int i = j*256 + tid;
        int k = i >> 4;
        int n0 = (i & 15) * 4;
        float4 v = *(const float4*)(x + (size_t)k*NTOT + n0blk + n0);
        unsigned short h0 = bfc(v.x,0), h1 = bfc(v.y,0), h2 = bfc(v.z,0), h3 = bfc(v.w,0);
        unsigned short l0 = bfc(v.x,1), l1 = bfc(v.y,1), l2 = bfc(v.z,1), l3 = bfc(v.w,1);
        u64 hq = (u64)h0 | ((u64)h1<<16) | ((u64)h2<<32) | ((u64)h3<<48);
        u64 lq = (u64)l0 | ((u64)l1<<16) | ((u64)l2<<32) | ((u64)l3<<48);
        int c = n0 >> 3;
        uint32_t off = (uint32_t)(k*128 + ((c ^ (k & 7)) << 4) + (n0 & 7)*2);
        *(u64*)(&sB[0][off]) = hq;
        *(u64*)(&sB[1][off]) = lq;
    }
    __syncthreads();

    uint32_t sb0 = smem_u32(sB[0]);
    uint32_t sb1 = smem_u32(sB[1]);
    int wid = tid >> 5, lane = tid & 31;
    int wm = wid & 3, wn = wid >> 2;
    int gid = lane >> 2, tig = lane & 3;
    int l16 = lane & 15;

    const uint4* wfh = wf + (((size_t)0*MT + mt)*8)*8*32;
    const uint4* wfl = wf + (((size_t)1*MT + mt)*8)*8*32;

    float acc[2][4][4];
#pragma unroll
    for (int m = 0; m < 2; m++)
#pragma unroll
        for (int n = 0; n < 4; n++)
#pragma unroll
            for (int q = 0; q < 4; q++) acc[m][n][q] = 0.f;

#pragma unroll
    for (int ks = 0; ks < 8; ks++){
        uint4 ah[2], al[2];
        ah[0] = wfh[((wm*2 + 0)*8 + ks)*32 + lane];
        ah[1] = wfh[((wm*2 + 1)*8 + ks)*32 + lane];
        al[0] = wfl[((wm*2 + 0)*8 + ks)*32 + lane];
        al[1] = wfl[((wm*2 + 1)*8 + ks)*32 + lane];
        uint32_t bh[4][2], bl[4][2];
        int krow = ks*16 + l16;
        uint32_t rowoff = (uint32_t)(krow * 128);
#pragma unroll
        for (int nn = 0; nn < 4; nn++){
            int c = wn*4 + nn;
            uint32_t off = rowoff + (uint32_t)(((c ^ (krow & 7)) << 4));
            ldm_x2_t(bh[nn][0], bh[nn][1], sb0 + off);
            ldm_x2_t(bl[nn][0], bl[nn][1], sb1 + off);
        }
#pragma unroll
        for (int mm = 0; mm < 2; mm++)
#pragma unroll
            for (int nn = 0; nn < 4; nn++){
                mma_bf16(acc[mm][nn], ah[mm], bh[nn]);
                mma_bf16(acc[mm][nn], ah[mm], bl[nn]);
                mma_bf16(acc[mm][nn], al[mm], bh[nn]);
            }
    }

    float* cb = C + ((size_t)(b*MT + mt) * 128) * NTOT + n0blk;
#pragma unroll
    for (int mm = 0; mm < 2; mm++)
#pragma unroll
        for (int nn = 0; nn < 4; nn++){
            int row0 = wm*32 + mm*16 + gid;
            int col0 = wn*32 + nn*8 + 2*tig;
            *(float2*)(cb + (size_t)row0*NTOT + col0)     = make_float2(acc[mm][nn][0], acc[mm][nn][1]);
            *(float2*)(cb + (size_t)(row0+8)*NTOT + col0) = make_float2(acc[mm][nn][2], acc[mm][nn][3]);
        }
}

// fused dwconv3x3 + sa gate + reductions + v write
__global__ void __launch_bounds__(256) k2_dw(const float* __restrict__ qkv_dw_w){
    int tid = threadIdx.x;
    int r = blockIdx.x, h = blockIdx.y, b = blockIdx.z;
    int g = tid >> 6, t = tid & 63;
    __shared__ __align__(16) float qs[16][268];
    __shared__ __align__(16) float ks[16][268];
    __shared__ float sdw[48][9];
    __shared__ __align__(16) float s_sa[256];
    __shared__ float s_ssq_q[16], s_ssq_k[16], s_vsum[16];

    if (tid < 64)
        *(float4*)(s_sa + 4*tid) = *(const float4*)(g_sa + (size_t)b*NTOT + r*256 + 4*tid);
    for (int idx = tid; idx < 432; idx += 256){
        int lc = idx / 9, j = idx % 9;
        int ch = (lc < 16) ? (h*16 + lc) : (lc < 32 ? (128 + h*16 + (lc-16)) : (256 + h*16 + (lc-32)));
        sdw[lc][j] = qkv_dw_w[ch*9 + j];
    }
    if (tid < 16){ s_ssq_q[tid] = 0.f; s_ssq_k[tid] = 0.f; s_vsum[tid] = 0.f; }
    __syncthreads();

    float4 sa4 = *(const float4*)(s_sa + 4*t);
    int lane = tid & 31;

    for (int lc0 = 0; lc0 < 48; lc0 += 4){
        int lc = lc0 + g;
        int ch = (lc < 16) ? (h*16 + lc) : (lc < 32 ? (128 + h*16 + (lc-16)) : (256 + h*16 + (lc-32)));
        const float* base = g_qkv1 + ((size_t)b*384 + ch) * NTOT;
        float4 v = conv3x4(base, r, t, sdw[lc]);
        if (lc < 16){
            v.x *= sa4.x; v.y *= sa4.y; v.z *= sa4.z; v.w *= sa4.w;
            *(float4*)&qs[lc][4*t] = v;
            float sq = v.x*v.x + v.y*v.y + v.z*v.z + v.w*v.w;
#pragma unroll
            for (int o = 16; o; o >>= 1) sq += __shfl_down_sync(0xffffffffu, sq, o);
            if (lane == 0) atomicAdd(&s_ssq_q[lc], sq);
        } else if (lc < 32){
            *(float4*)&ks[lc-16][4*t] = v;
            float sq = v.x*v.x + v.y*v.y + v.z*v.z + v.w*v.w;
#pragma unroll
            for (int o = 16; o; o >>= 1) sq += __shfl_down_sync(0xffffffffu, sq, o);
            if (lane == 0) atomicAdd(&s_ssq_k[lc-16], sq);
        } else {
            *(float4*)(g_v2 + ((size_t)b*128 + h*16 + (lc-32)) * NTOT + r*256 + 4*t) = v;
            float sv = v.x + v.y + v.z + v.w;
#pragma unroll
            for (int o = 16; o; o >>= 1) sv += __shfl_down_sync(0xffffffffu, sv, o);
            if (lane == 0) atomicAdd(&s_vsum[lc-32], sv);
        }
    }
    __syncthreads();

    int c = tid >> 4, d = tid & 15;
    float s = 0.f;
#pragma unroll 8
    for (int i = 0; i < 64; i++){
        float4 qv = *(const float4*)&qs[c][4*i];
        float4 kv = *(const float4*)&ks[d][4*i];
        s += qv.x*kv.x + qv.y*kv.y + qv.z*kv.z + qv.w*kv.w;
    }
    atomicAdd(&g_S[((b*8 + h)*16 + c)*16 + d], s);

    if (tid < 16){
        atomicAdd(&g_ssq_q[b*128 + h*16 + tid], s_ssq_q[tid]);
        atomicAdd(&g_ssq_k[b*128 + h*16 + tid], s_ssq_k[tid]);
        atomicAdd(&g_sumv [b*128 + h*16 + tid], s_vsum[tid]);
    }
}

// softmax + spectral MLP (one block, 256 threads)
__global__ void k4_small(const float* __restrict__ sp_w1, const float* __restrict__ sp_w2,
                         const float* __restrict__ sp_w3, const float* __restrict__ temp){
    __shared__ float pooled[2][128];
    __shared__ float t1s[2][16], t2s[2][16];
    int t = threadIdx.x;
    int b = t >> 7, row = t & 127, h = row >> 4, c = row & 15;

    float nq = fmaxf(sqrtf(g_ssq_q[b*128 + row]), 1e-12f);
    float tmp = temp[h];
    float logits[16];
    float mx = -1e30f;
#pragma unroll
    for (int d = 0; d < 16; d++){
        float nk = fmaxf(sqrtf(g_ssq_k[b*128 + h*16 + d]), 1e-12f);
        float L = g_S[((b*8 + h)*16 + c)*16 + d] / (nq * nk) * tmp;
        logits[d] = L; mx = fmaxf(mx, L);
    }
    float se = 0.f;
#pragma unroll
    for (int d = 0; d < 16; d++){ float e = expf(logits[d] - mx); logits[d] = e; se += e; }
    float inv = 1.f / se;
    float pool = 0.f;
#pragma unroll
    for (int d = 0; d < 16; d++){
        float a = logits[d] * inv;
        g_attn[b*2048 + (h*16 + c)*16 + d] = a;
        pool += a * g_sumv[b*128 + h*16 + d];
    }
    pooled[b][row] = pool * (1.f / 65536.f);
    __syncthreads();
    if (t < 32){
        int bb = t >> 4, j = t & 15;
        float s = 0.f;
        for (int c2 = 0; c2 < 128; c2++) s += sp_w1[j*128 + c2] * pooled[bb][c2];
        t1s[bb][j] = gelu_exact(s);
    }
    __syncthreads();
    if (t < 32){
        int bb = t >> 4, j = t & 15;
        float s = 0.f;
#pragma unroll
        for (int i = 0; i < 16; i++) s += sp_w2[j*16 + i] * t1s[bb][i];
        t2s[bb][j] = gelu_exact(s);
    }
    __syncthreads();
    {
        int bb = t >> 7, ch = t & 127;
        float s = 0.f;
#pragma unroll
        for (int j = 0; j < 16; j++) s += sp_w3[ch*16 + j] * t2s[bb][j];
        g_spec[bb*128 + ch] = 1.f / (1.f + expf(-s));
    }
}

// z = blockdiag(attn) @ v + spec * dwconv3x3(y); one (row, head) per block, 1 sync
__global__ void __launch_bounds__(256) k5b_z(const float* __restrict__ y,
                                             const float* __restrict__ dw_w){
    int tid = threadIdx.x;
    int r = blockIdx.x, h = blockIdx.y, b = blockIdx.z;
    int g = tid >> 6, t = tid & 63;
    __shared__ __align__(16) float sv[16][260];
    __shared__ float s_attn[256];
    __shared__ float s_dw[16][9];
    __shared__ float s_spec[16];

    s_attn[tid] = g_attn[b*2048 + h*256 + tid];
    if (tid < 144) (&s_dw[0][0])[tid] = dw_w[h*144 + tid];
    if (tid < 16)  s_spec[tid] = g_spec[b*128 + h*16 + tid];
    for (int i = tid; i < 1024; i += 256){
        int d = i >> 6, p = i & 63;
        *(float4*)&sv[d][4*p] =
            *(const float4*)(g_v2 + ((size_t)b*128 + h*16 + d) * NTOT + (size_t)r*256 + 4*p);
    }
    __syncthreads();

#pragma unroll
    for (int cc = 0; cc < 4; cc++){
        int c = cc*4 + g;
        int ch = h*16 + c;
        const float* ybase = y + ((size_t)b*128 + ch) * NTOT;
        float4 z = conv3x4(ybase, r, t, s_dw[c]);
        float sp = s_spec[c];
        z.x *= sp; z.y *= sp; z.z *= sp; z.w *= sp;
        const float* arow = &s_attn[c * 16];
#pragma unroll
        for (int d = 0; d < 16; d++){
            float a = arow[d];
            float4 vd = *(const float4*)&sv[d][4*t];
            z.x += a*vd.x; z.y += a*vd.y; z.z += a*vd.z; z.w += a*vd.w;
        }
        *(float4*)(g_z + ((size_t)b*128 + ch) * NTOT + (size_t)r*256 + 4*t) = z;
    }
}

extern "C" void kernel_launch(void* const* d_in, const int* in_sizes, int n_in,
                              void* d_out, int out_size){
    const float* x        = (const float*)d_in[0];
    const float* y        = (const float*)d_in[1];
    const float* qkv_w    = (const float*)d_in[2];
    const float* qkv_dw_w = (const float*)d_in[3];
    const float* proj_w   = (const float*)d_in[4];
    const float* sa_w1    = (const float*)d_in[5];
    const float* sa_w2    = (const float*)d_in[6];
    const float* sa_w3    = (const float*)d_in[7];
    const float* sp_w1    = (const float*)d_in[8];
    const float* sp_w2    = (const float*)d_in[9];
    const float* sp_w3    = (const float*)d_in[10];
    const float* dw_w     = (const float*)d_in[11];
    const float* temp     = (const float*)d_in[12];
    float* out = (float*)d_out;

    float *qkv1, *z;
    uint4 *wfq, *wfp;
    cudaGetSymbolAddress((void**)&qkv1, g_qkv1);
    cudaGetSymbolAddress((void**)&z,    g_z);
    cudaGetSymbolAddress((void**)&wfq,  g_wfrag_q);
    cudaGetSymbolAddress((void**)&wfp,  g_wfrag_p);

    k_prep<<<83, 256>>>(qkv_w, proj_w);
    k_sa<<<dim3(128, 2), 256>>>(y, sa_w1, sa_w2, sa_w3);
    k_mma<<<dim3(1024, 3, 2), 256>>>(x, qkv1, wfq, 3);
    k2_dw<<<dim3(256, 8, 2), 256>>>(qkv_dw_w);
    k4_small<<<1, 256>>>(sp_w1, sp_w2, sp_w3, temp);
    k5b_z<<<dim3(256, 8, 2), 256>>>(y, dw_w);
    k_mma<<<dim3(1024, 1, 2), 256>>>(z, out, wfp, 1);
}